// round 2
// baseline (speedup 1.0000x reference)
#include <cuda_runtime.h>
#include <cstdint>

// Problem dims
#define B_SZ 64
#define T_SZ 512
#define D_SZ 1024
#define R_SZ 1024
#define O_SZ 1024
#define M_SZ (B_SZ * T_SZ)   // 32768

// ---------------- device scratch (static: no runtime allocation) ----------------
__device__ float g_xh[(size_t)T_SZ * B_SZ * R_SZ];   // [T][B][R]  128 MB
__device__ float g_xz[(size_t)T_SZ * B_SZ * R_SZ];   // [T][B][R]  128 MB
__device__ float g_Mz[(size_t)R_SZ * R_SZ];          // Wxz @ Whz   4 MB
__device__ float g_h[2][B_SZ * R_SZ];                // double-buffered state
__device__ unsigned g_arrive;                        // grid barrier counter

__device__ __forceinline__ void dot4(float& acc, const float4& h, const float4& w) {
    acc = fmaf(h.x, w.x, acc);
    acc = fmaf(h.y, w.y, acc);
    acc = fmaf(h.z, w.z, acc);
    acc = fmaf(h.w, w.w, acc);
}

// ---------------- init: reset per-replay state ----------------
__global__ void init_kernel() {
    int i = blockIdx.x * blockDim.x + threadIdx.x;
    if (i < B_SZ * R_SZ) g_h[0][i] = 0.0f;
    if (i == 0) g_arrive = 0u;
}

// ---------------- Mz = Wxz @ Whz  (NN gemm, 1024^3) ----------------
// 64x64 tile, BK=16, 256 threads, 4x4 per thread
__global__ void __launch_bounds__(256) mz_kernel(const float* __restrict__ Wxz,
                                                 const float* __restrict__ Whz) {
    __shared__ float As[16][68];   // As[k][i]
    __shared__ float Bs[16][68];   // Bs[k][j]
    const int tid = threadIdx.x;
    const int i0 = blockIdx.x * 64;
    const int j0 = blockIdx.y * 64;

    const int tx = tid & 15;        // j / 4
    const int ty = tid >> 4;        // i / 4
    float acc[4][4] = {};

    for (int k0 = 0; k0 < R_SZ; k0 += 16) {
        // A tile: Wxz[i0+row][k0 + c4*4 .. +3]  (K-contiguous)
        {
            int row = tid >> 2;
            int c4  = (tid & 3) * 4;
            float4 a = *(const float4*)(Wxz + (size_t)(i0 + row) * R_SZ + k0 + c4);
            As[c4 + 0][row] = a.x; As[c4 + 1][row] = a.y;
            As[c4 + 2][row] = a.z; As[c4 + 3][row] = a.w;
        }
        // B tile: Whz[k0+kk][j0 + j4*4 .. +3] (N-contiguous)
        {
            int kk = tid >> 4;
            int j4 = (tid & 15) * 4;
            float4 b = *(const float4*)(Whz + (size_t)(k0 + kk) * R_SZ + j0 + j4);
            *(float4*)&Bs[kk][j4] = b;
        }
        __syncthreads();
        #pragma unroll
        for (int kk = 0; kk < 16; kk++) {
            float ar[4], br[4];
            *(float4*)ar = *(const float4*)&As[kk][ty * 4];
            *(float4*)br = *(const float4*)&Bs[kk][tx * 4];
            #pragma unroll
            for (int i = 0; i < 4; i++)
                #pragma unroll
                for (int j = 0; j < 4; j++)
                    acc[i][j] = fmaf(ar[i], br[j], acc[i][j]);
        }
        __syncthreads();
    }
    #pragma unroll
    for (int i = 0; i < 4; i++) {
        float4 v = make_float4(acc[i][0], acc[i][1], acc[i][2], acc[i][3]);
        *(float4*)(g_Mz + (size_t)(i0 + ty * 4 + i) * R_SZ + j0 + tx * 4) = v;
    }
}

// ---------------- Precompute xh / xz: C = X @ W^T + bias  ----------------
// 128x128 tile, BK=16, 256 threads, 8x8 per thread.
// N dim is 2048 = [Wxh rows | Wxz rows]; output written in [T][B][R] layout.
__global__ void __launch_bounds__(256) precompute_kernel(
    const float* __restrict__ x,   const float* __restrict__ Wxh,
    const float* __restrict__ Wxz, const float* __restrict__ bh,
    const float* __restrict__ bz) {
    __shared__ float As[16][132];  // [k][m]
    __shared__ float Bs[16][132];  // [k][n]
    const int tid = threadIdx.x;
    const long m0 = (long)blockIdx.x * 128;
    const int  n0 = blockIdx.y * 128;

    const float* W;  const float* bias;  float* dst;  int r0;
    if (n0 < R_SZ) { W = Wxh; bias = bh; dst = g_xh; r0 = n0; }
    else           { W = Wxz; bias = bz; dst = g_xz; r0 = n0 - R_SZ; }

    const int tx = tid & 15;   // n / 8
    const int ty = tid >> 4;   // m / 8
    float acc[8][8] = {};

    for (int k0 = 0; k0 < D_SZ; k0 += 16) {
        #pragma unroll
        for (int l = 0; l < 2; l++) {
            int lin = tid + l * 256;     // 512 float4 loads per operand tile
            int row = lin >> 2;          // 0..127
            int c4  = (lin & 3) * 4;     // 0,4,8,12
            float4 a = *(const float4*)(x + (m0 + row) * (long)D_SZ + k0 + c4);
            float4 b = *(const float4*)(W + (size_t)(r0 + row) * D_SZ + k0 + c4);
            As[c4 + 0][row] = a.x; As[c4 + 1][row] = a.y;
            As[c4 + 2][row] = a.z; As[c4 + 3][row] = a.w;
            Bs[c4 + 0][row] = b.x; Bs[c4 + 1][row] = b.y;
            Bs[c4 + 2][row] = b.z; Bs[c4 + 3][row] = b.w;
        }
        __syncthreads();
        #pragma unroll
        for (int kk = 0; kk < 16; kk++) {
            float ar[8], br[8];
            *(float4*)&ar[0] = *(const float4*)&As[kk][ty * 8];
            *(float4*)&ar[4] = *(const float4*)&As[kk][ty * 8 + 4];
            *(float4*)&br[0] = *(const float4*)&Bs[kk][tx * 8];
            *(float4*)&br[4] = *(const float4*)&Bs[kk][tx * 8 + 4];
            #pragma unroll
            for (int i = 0; i < 8; i++)
                #pragma unroll
                for (int j = 0; j < 8; j++)
                    acc[i][j] = fmaf(ar[i], br[j], acc[i][j]);
        }
        __syncthreads();
    }

    // epilogue: + bias, scatter to [T][B][R]
    float bb[8];
    *(float4*)&bb[0] = *(const float4*)(bias + r0 + tx * 8);
    *(float4*)&bb[4] = *(const float4*)(bias + r0 + tx * 8 + 4);
    #pragma unroll
    for (int i = 0; i < 8; i++) {
        long m   = m0 + ty * 8 + i;
        int bidx = (int)(m >> 9);       // m / T
        int t    = (int)(m & 511);      // m % T
        float* orow = dst + ((long)t * B_SZ + bidx) * R_SZ + r0 + tx * 8;
        float4 v0 = make_float4(acc[i][0] + bb[0], acc[i][1] + bb[1],
                                acc[i][2] + bb[2], acc[i][3] + bb[3]);
        float4 v1 = make_float4(acc[i][4] + bb[4], acc[i][5] + bb[5],
                                acc[i][6] + bb[6], acc[i][7] + bb[7]);
        *(float4*)(orow + 0) = v0;
        *(float4*)(orow + 4) = v1;
    }
}

// ---------------- Persistent scan kernel ----------------
// 128 blocks x 128 threads. Block owns 8 R-rows of Whh and Mz (SMEM-resident,
// loaded once). Per step: stage h in 4 SMEM chunks, accumulate 4 dot products
// per thread (2 batches x 2 rows x 2 matrices), apply gate, software grid sync.
#define SCAN_BLOCKS 128
#define SW_STRIDE 1036            // 1024 + pad (bank shift 12)
#define SH_STRIDE 260             // 256 + pad (bank shift 4)
#define SCAN_SMEM ((16 * SW_STRIDE + 64 * SH_STRIDE) * 4)

__global__ void __launch_bounds__(128) scan_kernel(const float* __restrict__ Whh) {
    extern __shared__ float smem[];
    float* sW = smem;                       // 16 rows: [0..7]=Whh, [8..15]=Mz
    float* sh = smem + 16 * SW_STRIDE;      // h chunk [64][256]

    const int tid = threadIdx.x;
    const int r0  = blockIdx.x * 8;

    // load weights once (16 rows x 1024 = 4096 float4)
    #pragma unroll
    for (int v = 0; v < 32; v++) {
        int lin4 = tid + v * 128;
        int row  = lin4 >> 8;
        int c    = (lin4 & 255) * 4;
        const float* src = (row < 8)
            ? (Whh  + (size_t)(r0 + row)     * R_SZ + c)
            : (g_Mz + (size_t)(r0 + row - 8) * R_SZ + c);
        *(float4*)&sW[row * SW_STRIDE + c] = *(const float4*)src;
    }
    __syncthreads();

    const int bq = tid >> 2;           // 0..31
    const int rq = tid & 3;            // 0..3
    const int b0 = bq, b1 = bq + 32;
    const int ra = rq * 2, rb = rq * 2 + 1;
    const float* wh_a = &sW[ra * SW_STRIDE];
    const float* wh_b = &sW[rb * SW_STRIDE];
    const float* wz_a = &sW[(8 + ra) * SW_STRIDE];
    const float* wz_b = &sW[(8 + rb) * SW_STRIDE];

    for (int t = 0; t < T_SZ; t++) {
        const float* hin  = g_h[t & 1];
        float*       hout = g_h[(t + 1) & 1];

        float ah[2][2] = {}, az[2][2] = {};

        for (int kc = 0; kc < R_SZ; kc += 256) {
            __syncthreads();   // previous chunk readers done
            // stage h[0:64][kc:kc+256] (L1-bypassing: cross-block coherence)
            #pragma unroll
            for (int v = 0; v < 32; v++) {
                int lin4 = tid + v * 128;
                int row  = lin4 >> 6;
                int c    = (lin4 & 63) * 4;
                float4 h4 = __ldcg((const float4*)(hin + (size_t)row * R_SZ + kc + c));
                *(float4*)&sh[row * SH_STRIDE + c] = h4;
            }
            __syncthreads();

            #pragma unroll 8
            for (int k4 = 0; k4 < 64; k4++) {
                float4 h0 = *(const float4*)&sh[b0 * SH_STRIDE + k4 * 4];
                float4 h1 = *(const float4*)&sh[b1 * SH_STRIDE + k4 * 4];
                int kg = kc + k4 * 4;
                float4 wha = *(const float4*)&wh_a[kg];
                float4 whb = *(const float4*)&wh_b[kg];
                float4 wza = *(const float4*)&wz_a[kg];
                float4 wzb = *(const float4*)&wz_b[kg];
                dot4(ah[0][0], h0, wha); dot4(ah[0][1], h0, whb);
                dot4(ah[1][0], h1, wha); dot4(ah[1][1], h1, whb);
                dot4(az[0][0], h0, wza); dot4(az[0][1], h0, wzb);
                dot4(az[1][0], h1, wza); dot4(az[1][1], h1, wzb);
            }
        }

        // gate + write h_new for 4 (b, r) outputs
        const float* xh_t = g_xh + (size_t)t * (B_SZ * R_SZ);
        const float* xz_t = g_xz + (size_t)t * (B_SZ * R_SZ);
        #pragma unroll
        for (int bi = 0; bi < 2; bi++) {
            int b = (bi == 0) ? b0 : b1;
            #pragma unroll
            for (int ri = 0; ri < 2; ri++) {
                int rg = r0 + ((ri == 0) ? ra : rb);
                int idx = b * R_SZ + rg;
                float a_z = (ri == 0) ? az[bi][0] : az[bi][1];
                float a_h = (ri == 0) ? ah[bi][0] : ah[bi][1];
                float pz = a_z + __ldg(&xz_t[idx]);
                float z  = 1.0f / (1.0f + expf(-pz));
                float ph = a_h + __ldg(&xh_t[idx]);
                float hb = ph > 0.0f ? ph : 0.0f;
                float ho = __ldcg(&hin[idx]);
                hout[idx] = z * ho + (1.0f - z) * hb;
            }
        }

        // software grid barrier (monotonic counter; reset by init_kernel)
        __syncthreads();
        if (tid == 0) {
            __threadfence();
            atomicAdd(&g_arrive, 1u);
            unsigned target = (unsigned)SCAN_BLOCKS * (unsigned)(t + 1);
            while (*((volatile unsigned*)&g_arrive) < target) { }
        }
        __syncthreads();
    }
}

// ---------------- Output: y = h_final @ Wy^T + by ----------------
__global__ void __launch_bounds__(128) output_kernel(const float* __restrict__ Wy,
                                                     const float* __restrict__ by,
                                                     float* __restrict__ out) {
    __shared__ float shh[R_SZ];
    const int b = blockIdx.x;
    const int o = blockIdx.y * 128 + threadIdx.x;
    const float* hrow = g_h[0] + (size_t)b * R_SZ;   // final h lives in buffer 0 (T even)
    #pragma unroll
    for (int v = 0; v < 2; v++) {
        int i4 = threadIdx.x + v * 128;
        ((float4*)shh)[i4] = *(const float4*)(hrow + i4 * 4);
    }
    __syncthreads();
    float acc = __ldg(&by[o]);
    const float* wrow = Wy + (size_t)o * R_SZ;
    #pragma unroll 8
    for (int k4 = 0; k4 < R_SZ / 4; k4++) {
        float4 h4 = ((const float4*)shh)[k4];
        float4 w4 = __ldg((const float4*)(wrow + k4 * 4));
        acc = fmaf(h4.x, w4.x, acc); acc = fmaf(h4.y, w4.y, acc);
        acc = fmaf(h4.z, w4.z, acc); acc = fmaf(h4.w, w4.w, acc);
    }
    out[(size_t)b * O_SZ + o] = acc;
}

// ---------------- launch ----------------
extern "C" void kernel_launch(void* const* d_in, const int* in_sizes, int n_in,
                              void* d_out, int out_size) {
    const float* x   = (const float*)d_in[0];
    const float* Wxh = (const float*)d_in[1];
    const float* bh  = (const float*)d_in[2];
    const float* Whh = (const float*)d_in[3];
    const float* Wxz = (const float*)d_in[4];
    const float* bz  = (const float*)d_in[5];
    const float* Whz = (const float*)d_in[6];
    const float* Wy  = (const float*)d_in[7];
    const float* by  = (const float*)d_in[8];
    float* out = (float*)d_out;

    static bool attr_set = false;
    if (!attr_set) {
        cudaFuncSetAttribute(scan_kernel,
                             cudaFuncAttributeMaxDynamicSharedMemorySize, SCAN_SMEM);
        attr_set = true;
    }

    // Mz = Wxz @ Whz
    mz_kernel<<<dim3(R_SZ / 64, R_SZ / 64), 256>>>(Wxz, Whz);
    // xh, xz precompute (N = 2048 concat)
    precompute_kernel<<<dim3(M_SZ / 128, 2048 / 128), 256>>>(x, Wxh, Wxz, bh, bz);
    // reset h0 and barrier
    init_kernel<<<(B_SZ * R_SZ + 255) / 256, 256>>>();
    // persistent recurrent scan
    scan_kernel<<<SCAN_BLOCKS, 128, SCAN_SMEM>>>(Whh);
    // y = h @ Wy^T + by
    output_kernel<<<dim3(B_SZ, O_SZ / 128), 128>>>(Wy, by, out);
}

// round 5
// speedup vs baseline: 1.4756x; 1.4756x over previous
#include <cuda_runtime.h>
#include <cuda_bf16.h>
#include <cstdint>

// Problem dims
#define B_SZ 64
#define T_SZ 512
#define D_SZ 1024
#define R_SZ 1024
#define O_SZ 1024
#define M_SZ (B_SZ * T_SZ)   // 32768

// ---------------- device scratch (static: no runtime allocation) ----------------
__device__ float    g_xh[(size_t)T_SZ * B_SZ * R_SZ];   // [T][B][R]
__device__ float    g_xz[(size_t)T_SZ * B_SZ * R_SZ];   // [T][B][R]
__device__ float    g_Mz[(size_t)R_SZ * R_SZ];          // Wxz @ Whz
__device__ uint32_t g_hx[2][B_SZ * R_SZ];               // packed (bf16 hi | bf16 lo<<16)
__device__ float    g_hf[B_SZ * R_SZ];                  // final h fp32
__device__ unsigned g_arrive;                           // grid barrier counter

// ==================== helpers ====================
__device__ __forceinline__ uint32_t smem_u32(const void* p) {
    uint32_t a;
    asm("{ .reg .u64 t; cvta.to.shared.u64 t, %1; cvt.u32.u64 %0, t; }" : "=r"(a) : "l"(p));
    return a;
}
__device__ __forceinline__ void ldsm_x4(uint32_t r[4], uint32_t addr) {
    asm volatile("ldmatrix.sync.aligned.m8n8.x4.shared.b16 {%0,%1,%2,%3}, [%4];"
                 : "=r"(r[0]), "=r"(r[1]), "=r"(r[2]), "=r"(r[3]) : "r"(addr));
}
__device__ __forceinline__ void mma_bf16(float d[4], const uint32_t a[4],
                                         uint32_t b0, uint32_t b1) {
    asm volatile("mma.sync.aligned.m16n8k16.row.col.f32.bf16.bf16.f32 "
                 "{%0,%1,%2,%3}, {%4,%5,%6,%7}, {%8,%9}, {%0,%1,%2,%3};"
                 : "+f"(d[0]), "+f"(d[1]), "+f"(d[2]), "+f"(d[3])
                 : "r"(a[0]), "r"(a[1]), "r"(a[2]), "r"(a[3]), "r"(b0), "r"(b1));
}
__device__ __forceinline__ uint32_t pack_bf16_split(float v) {
    __nv_bfloat16 h = __float2bfloat16_rn(v);
    float r = v - __bfloat162float(h);
    __nv_bfloat16 l = __float2bfloat16_rn(r);
    return (uint32_t)__bfloat16_as_ushort(h) | ((uint32_t)__bfloat16_as_ushort(l) << 16);
}

// ==================== init: reset per-replay state ====================
__global__ void init_kernel() {
    int i = blockIdx.x * blockDim.x + threadIdx.x;
    if (i < B_SZ * R_SZ) g_hx[0][i] = 0u;
    if (i == 0) g_arrive = 0u;
}

// ==================== Mz = Wxz @ Whz ====================
__global__ void __launch_bounds__(256) mz_kernel(const float* __restrict__ Wxz,
                                                 const float* __restrict__ Whz) {
    __shared__ float As[16][68];
    __shared__ float Bs[16][68];
    const int tid = threadIdx.x;
    const int i0 = blockIdx.x * 64;
    const int j0 = blockIdx.y * 64;
    const int tx = tid & 15;
    const int ty = tid >> 4;
    float acc[4][4] = {};

    for (int k0 = 0; k0 < R_SZ; k0 += 16) {
        {
            int row = tid >> 2;
            int c4  = (tid & 3) * 4;
            float4 a = *(const float4*)(Wxz + (size_t)(i0 + row) * R_SZ + k0 + c4);
            As[c4 + 0][row] = a.x; As[c4 + 1][row] = a.y;
            As[c4 + 2][row] = a.z; As[c4 + 3][row] = a.w;
        }
        {
            int kk = tid >> 4;
            int j4 = (tid & 15) * 4;
            float4 b = *(const float4*)(Whz + (size_t)(k0 + kk) * R_SZ + j0 + j4);
            *(float4*)&Bs[kk][j4] = b;
        }
        __syncthreads();
        #pragma unroll
        for (int kk = 0; kk < 16; kk++) {
            float ar[4], br[4];
            *(float4*)ar = *(const float4*)&As[kk][ty * 4];
            *(float4*)br = *(const float4*)&Bs[kk][tx * 4];
            #pragma unroll
            for (int i = 0; i < 4; i++)
                #pragma unroll
                for (int j = 0; j < 4; j++)
                    acc[i][j] = fmaf(ar[i], br[j], acc[i][j]);
        }
        __syncthreads();
    }
    #pragma unroll
    for (int i = 0; i < 4; i++) {
        float4 v = make_float4(acc[i][0], acc[i][1], acc[i][2], acc[i][3]);
        *(float4*)(g_Mz + (size_t)(i0 + ty * 4 + i) * R_SZ + j0 + tx * 4) = v;
    }
}

// ==================== Precompute xh/xz (SIMT fp32) ====================
__global__ void __launch_bounds__(256) precompute_kernel(
    const float* __restrict__ x,   const float* __restrict__ Wxh,
    const float* __restrict__ Wxz, const float* __restrict__ bh,
    const float* __restrict__ bz) {
    __shared__ float As[16][132];
    __shared__ float Bs[16][132];
    const int tid = threadIdx.x;
    const long m0 = (long)blockIdx.x * 128;
    const int  n0 = blockIdx.y * 128;

    const float* W;  const float* bias;  float* dst;  int r0;
    if (n0 < R_SZ) { W = Wxh; bias = bh; dst = g_xh; r0 = n0; }
    else           { W = Wxz; bias = bz; dst = g_xz; r0 = n0 - R_SZ; }

    const int tx = tid & 15;
    const int ty = tid >> 4;
    float acc[8][8] = {};

    for (int k0 = 0; k0 < D_SZ; k0 += 16) {
        #pragma unroll
        for (int l = 0; l < 2; l++) {
            int lin = tid + l * 256;
            int row = lin >> 2;
            int c4  = (lin & 3) * 4;
            float4 a = *(const float4*)(x + (m0 + row) * (long)D_SZ + k0 + c4);
            float4 b = *(const float4*)(W + (size_t)(r0 + row) * D_SZ + k0 + c4);
            As[c4 + 0][row] = a.x; As[c4 + 1][row] = a.y;
            As[c4 + 2][row] = a.z; As[c4 + 3][row] = a.w;
            Bs[c4 + 0][row] = b.x; Bs[c4 + 1][row] = b.y;
            Bs[c4 + 2][row] = b.z; Bs[c4 + 3][row] = b.w;
        }
        __syncthreads();
        #pragma unroll
        for (int kk = 0; kk < 16; kk++) {
            float ar[8], br[8];
            *(float4*)&ar[0] = *(const float4*)&As[kk][ty * 8];
            *(float4*)&ar[4] = *(const float4*)&As[kk][ty * 8 + 4];
            *(float4*)&br[0] = *(const float4*)&Bs[kk][tx * 8];
            *(float4*)&br[4] = *(const float4*)&Bs[kk][tx * 8 + 4];
            #pragma unroll
            for (int i = 0; i < 8; i++)
                #pragma unroll
                for (int j = 0; j < 8; j++)
                    acc[i][j] = fmaf(ar[i], br[j], acc[i][j]);
        }
        __syncthreads();
    }

    float bb[8];
    *(float4*)&bb[0] = *(const float4*)(bias + r0 + tx * 8);
    *(float4*)&bb[4] = *(const float4*)(bias + r0 + tx * 8 + 4);
    #pragma unroll
    for (int i = 0; i < 8; i++) {
        long m   = m0 + ty * 8 + i;
        int bidx = (int)(m >> 9);
        int t    = (int)(m & 511);
        float* orow = dst + ((long)t * B_SZ + bidx) * R_SZ + r0 + tx * 8;
        float4 v0 = make_float4(acc[i][0] + bb[0], acc[i][1] + bb[1],
                                acc[i][2] + bb[2], acc[i][3] + bb[3]);
        float4 v1 = make_float4(acc[i][4] + bb[4], acc[i][5] + bb[5],
                                acc[i][6] + bb[6], acc[i][7] + bb[7]);
        *(float4*)(orow + 0) = v0;
        *(float4*)(orow + 4) = v1;
    }
}

// ==================== Persistent warp-MMA scan ====================
// 64 CTAs x 128 threads. CTA i owns r-slice [i*16, i*16+16).
// B (SMEM resident): 32 rows = [Whh slice (16) ; Mz slice (16)], bf16 hi+lo.
// Per step: D[64x32] = h[64x1024] @ B^T via 3 bf16 HMMA passes (hi*hi+hi*lo+lo*hi).
// Warp w (0..3): m0 = (w&1)*32, nh = (w>>1)*8; n-tiles {nh, 16+nh} -> gate stays in-warp.
#define NCTA 64
#define KC 64
#define NCHUNK (R_SZ / KC)                   // 16
#define B_ROW_E 1032                         // B row stride (elements), pad 8
#define B_ROW_BYTES (B_ROW_E * 2)            // 2064
#define A_ROW_E 72                           // A row stride (elements), pad 8
#define A_ROW_BYTES (A_ROW_E * 2)            // 144
#define A_PLANE_SZ (64 * A_ROW_BYTES)        // 9216
#define OFF_BHI 0
#define OFF_BLO (32 * B_ROW_BYTES)           // 66048
#define OFF_A   (2 * 32 * B_ROW_BYTES)       // 132096
#define SCAN_SMEM (OFF_A + 4 * A_PLANE_SZ)   // 168960

__global__ void __launch_bounds__(128) scan_kernel(const float* __restrict__ Whh) {
    extern __shared__ char smem[];
    const uint32_t sbase = smem_u32(smem);
    const int tid  = threadIdx.x;
    const int warp = tid >> 5;
    const int lane = tid & 31;
    const int r_base = blockIdx.x * 16;

    // ---- one-time: weights -> SMEM bf16 hi/lo ----
    for (int i = tid; i < 32 * R_SZ; i += 128) {
        int j = i >> 10;          // B row 0..31
        int k = i & 1023;         // K index
        float w = (j < 16) ? Whh[(size_t)(r_base + j) * R_SZ + k]
                           : g_Mz[(size_t)(r_base + j - 16) * R_SZ + k];
        __nv_bfloat16 h = __float2bfloat16_rn(w);
        __nv_bfloat16 l = __float2bfloat16_rn(w - __bfloat162float(h));
        *(unsigned short*)(smem + OFF_BHI + j * B_ROW_BYTES + k * 2) = __bfloat16_as_ushort(h);
        *(unsigned short*)(smem + OFF_BLO + j * B_ROW_BYTES + k * 2) = __bfloat16_as_ushort(l);
    }
    __syncthreads();

    // warp tile coords
    const int m0 = (warp & 1) * 32;          // batch rows [m0, m0+32)
    const int nh = (warp >> 1) * 8;          // h-cols [nh, nh+8), z-cols 16+nh

    // per-thread output ownership: 4 rows x 2 cols
    const int rrow = lane >> 2;              // 0..7  (D row in octet / B n index)
    const int jc   = (lane & 3) * 2;         // 0,2,4,6 (D col pair / B k pair)
    const int jg   = r_base + nh + jc;       // global r index (h/z col)
    int brow[4];
    #pragma unroll
    for (int q = 0; q < 4; q++) brow[q] = m0 + (q >> 1) * 16 + (q & 1) * 8 + rrow;

    // B fragment SMEM byte offsets (k16 offset added per-iteration)
    const uint32_t b_nh_off = (uint32_t)(nh + rrow) * B_ROW_BYTES + (uint32_t)jc * 2;
    const uint32_t b_nz_off = (uint32_t)(16 + nh + rrow) * B_ROW_BYTES + (uint32_t)jc * 2;

    // ldmatrix A addresses: row = m0 + mi*16 + (lane&15), col halves by lane>>4
    const uint32_t a_row_off = (uint32_t)(lane & 15) * A_ROW_BYTES + (uint32_t)(lane >> 4) * 16;

    float hold[4][2];
    #pragma unroll
    for (int q = 0; q < 4; q++) { hold[q][0] = 0.0f; hold[q][1] = 0.0f; }

    for (int t = 0; t < T_SZ; t++) {
        // prefetch xh/xz for owned elements
        float xh[4][2], xz[4][2];
        {
            const float* xh_t = g_xh + (size_t)t * (B_SZ * R_SZ);
            const float* xz_t = g_xz + (size_t)t * (B_SZ * R_SZ);
            #pragma unroll
            for (int q = 0; q < 4; q++) {
                float2 a = __ldg((const float2*)(xh_t + (size_t)brow[q] * R_SZ + jg));
                float2 c = __ldg((const float2*)(xz_t + (size_t)brow[q] * R_SZ + jg));
                xh[q][0] = a.x; xh[q][1] = a.y;
                xz[q][0] = c.x; xz[q][1] = c.y;
            }
        }

        const uint32_t* hsrc = g_hx[t & 1];

        // D accumulators: [mtile][ntile(0=h,1=z)][4]
        float d[2][2][4];
        #pragma unroll
        for (int a = 0; a < 2; a++)
            #pragma unroll
            for (int b = 0; b < 2; b++)
                #pragma unroll
                for (int c = 0; c < 4; c++) d[a][b][c] = 0.0f;

        // stage chunk 0: 64 rows x 64 cols = 2048 uint2 items (16 iters x 128 thr)
        {
            #pragma unroll
            for (int it = 0; it < 16; it++) {
                int item = tid + it * 128;          // 0..2047
                int b  = item >> 5;                 // batch row 0..63
                int kk = (item & 31) * 2;           // even col within chunk
                uint2 v = __ldcg((const uint2*)(hsrc + (size_t)b * R_SZ + 0 + kk));
                uint32_t hp = (v.x & 0xFFFFu) | (v.y << 16);
                uint32_t lp = (v.x >> 16) | (v.y & 0xFFFF0000u);
                uint32_t off = (uint32_t)b * A_ROW_BYTES + (uint32_t)kk * 2;
                *(uint32_t*)(smem + OFF_A + off) = hp;                 // buf0 hi
                *(uint32_t*)(smem + OFF_A + A_PLANE_SZ + off) = lp;    // buf0 lo
            }
        }
        __syncthreads();

        for (int c = 0; c < NCHUNK; c++) {
            const int cur = c & 1;
            // stage next chunk into other buffer
            if (c + 1 < NCHUNK) {
                const int nxt = (c + 1) & 1;
                const int rc = (c + 1) * KC;
                #pragma unroll
                for (int it = 0; it < 16; it++) {
                    int item = tid + it * 128;
                    int b  = item >> 5;
                    int kk = (item & 31) * 2;
                    uint2 v = __ldcg((const uint2*)(hsrc + (size_t)b * R_SZ + rc + kk));
                    uint32_t hp = (v.x & 0xFFFFu) | (v.y << 16);
                    uint32_t lp = (v.x >> 16) | (v.y & 0xFFFF0000u);
                    uint32_t off = (uint32_t)(nxt * 2) * A_PLANE_SZ + (uint32_t)b * A_ROW_BYTES + (uint32_t)kk * 2;
                    *(uint32_t*)(smem + OFF_A + off) = hp;
                    *(uint32_t*)(smem + OFF_A + off + A_PLANE_SZ) = lp;
                }
            }

            // compute current chunk: 4 k16 sub-iterations
            const uint32_t a_hi_base = sbase + OFF_A + (uint32_t)(cur * 2) * A_PLANE_SZ;
            const uint32_t a_lo_base = a_hi_base + A_PLANE_SZ;
            const uint32_t kglob = (uint32_t)(c * KC) * 2;   // byte offset of chunk in B rows

            #pragma unroll
            for (int kb = 0; kb < 4; kb++) {
                const uint32_t kloc = (uint32_t)(kb * 16) * 2;     // bytes within A chunk
                uint32_t ahi[2][4], alo[2][4];
                #pragma unroll
                for (int mi = 0; mi < 2; mi++) {
                    uint32_t arow = (uint32_t)(m0 + mi * 16) * A_ROW_BYTES + a_row_off + kloc;
                    ldsm_x4(ahi[mi], a_hi_base + arow);
                    ldsm_x4(alo[mi], a_lo_base + arow);
                }
                // B fragments (direct LDS u32)
                const char* bsm = smem;
                uint32_t kB = kglob + kloc;  // byte offset of k16 start in B row
                uint32_t bh0[2], bh1[2], bl0[2], bl1[2];
                bh0[0] = *(const uint32_t*)(bsm + OFF_BHI + b_nh_off + kB);
                bh1[0] = *(const uint32_t*)(bsm + OFF_BHI + b_nh_off + kB + 16);
                bh0[1] = *(const uint32_t*)(bsm + OFF_BHI + b_nz_off + kB);
                bh1[1] = *(const uint32_t*)(bsm + OFF_BHI + b_nz_off + kB + 16);
                bl0[0] = *(const uint32_t*)(bsm + OFF_BLO + b_nh_off + kB);
                bl1[0] = *(const uint32_t*)(bsm + OFF_BLO + b_nh_off + kB + 16);
                bl0[1] = *(const uint32_t*)(bsm + OFF_BLO + b_nz_off + kB);
                bl1[1] = *(const uint32_t*)(bsm + OFF_BLO + b_nz_off + kB + 16);

                #pragma unroll
                for (int mi = 0; mi < 2; mi++) {
                    #pragma unroll
                    for (int nt = 0; nt < 2; nt++) {
                        mma_bf16(d[mi][nt], ahi[mi], bh0[nt], bh1[nt]);
                        mma_bf16(d[mi][nt], ahi[mi], bl0[nt], bl1[nt]);
                        mma_bf16(d[mi][nt], alo[mi], bh0[nt], bh1[nt]);
                    }
                }
            }
            __syncthreads();
        }

        // gate epilogue: thread owns 4 rows x 2 cols
        uint32_t* hdst = g_hx[(t + 1) & 1];
        #pragma unroll
        for (int q = 0; q < 4; q++) {
            int mi = q >> 1;
            int ri = (q & 1) * 2;   // d reg base: 0 (row) or 2 (row+8)
            uint32_t pk[2];
            #pragma unroll
            for (int cc = 0; cc < 2; cc++) {
                float pre_h = d[mi][0][ri + cc] + xh[q][cc];
                float pre_z = d[mi][1][ri + cc] + xz[q][cc];
                float z  = 1.0f / (1.0f + expf(-pre_z));
                float hb = fmaxf(pre_h, 0.0f);
                float hn = z * hold[q][cc] + (1.0f - z) * hb;
                hold[q][cc] = hn;
                pk[cc] = pack_bf16_split(hn);
            }
            *(uint2*)(hdst + (size_t)brow[q] * R_SZ + jg) = make_uint2(pk[0], pk[1]);
            if (t == T_SZ - 1) {
                g_hf[(size_t)brow[q] * R_SZ + jg]     = hold[q][0];
                g_hf[(size_t)brow[q] * R_SZ + jg + 1] = hold[q][1];
            }
        }

        // grid barrier over 64 CTAs
        __threadfence();
        __syncthreads();
        if (tid == 0) {
            atomicAdd(&g_arrive, 1u);
            unsigned target = (unsigned)NCTA * (unsigned)(t + 1);
            while (*((volatile unsigned*)&g_arrive) < target) { }
            __threadfence();
        }
        __syncthreads();
    }
}

// ==================== Output: y = h_final @ Wy^T + by ====================
__global__ void __launch_bounds__(128) output_kernel(const float* __restrict__ Wy,
                                                     const float* __restrict__ by,
                                                     float* __restrict__ out) {
    __shared__ float shh[R_SZ];
    const int b = blockIdx.x;
    const int o = blockIdx.y * 128 + threadIdx.x;
    const float* hrow = g_hf + (size_t)b * R_SZ;
    #pragma unroll
    for (int v = 0; v < 2; v++) {
        int i4 = threadIdx.x + v * 128;
        ((float4*)shh)[i4] = *(const float4*)(hrow + i4 * 4);
    }
    __syncthreads();
    float acc = __ldg(&by[o]);
    const float* wrow = Wy + (size_t)o * R_SZ;
    #pragma unroll 8
    for (int k4 = 0; k4 < R_SZ / 4; k4++) {
        float4 h4 = ((const float4*)shh)[k4];
        float4 w4 = __ldg((const float4*)(wrow + k4 * 4));
        acc = fmaf(h4.x, w4.x, acc); acc = fmaf(h4.y, w4.y, acc);
        acc = fmaf(h4.z, w4.z, acc); acc = fmaf(h4.w, w4.w, acc);
    }
    out[(size_t)b * O_SZ + o] = acc;
}

// ==================== launch ====================
extern "C" void kernel_launch(void* const* d_in, const int* in_sizes, int n_in,
                              void* d_out, int out_size) {
    const float* x   = (const float*)d_in[0];
    const float* Wxh = (const float*)d_in[1];
    const float* bh  = (const float*)d_in[2];
    const float* Whh = (const float*)d_in[3];
    const float* Wxz = (const float*)d_in[4];
    const float* bz  = (const float*)d_in[5];
    const float* Whz = (const float*)d_in[6];
    const float* Wy  = (const float*)d_in[7];
    const float* by  = (const float*)d_in[8];
    float* out = (float*)d_out;

    static bool attr_set = false;
    if (!attr_set) {
        cudaFuncSetAttribute(scan_kernel,
                             cudaFuncAttributeMaxDynamicSharedMemorySize, SCAN_SMEM);
        attr_set = true;
    }

    mz_kernel<<<dim3(R_SZ / 64, R_SZ / 64), 256>>>(Wxz, Whz);
    precompute_kernel<<<dim3(M_SZ / 128, 2048 / 128), 256>>>(x, Wxh, Wxz, bh, bz);
    init_kernel<<<(B_SZ * R_SZ + 255) / 256, 256>>>();
    scan_kernel<<<NCTA, 128, SCAN_SMEM>>>(Whh);
    output_kernel<<<dim3(B_SZ, O_SZ / 128), 128>>>(Wy, by, out);
}

// round 6
// speedup vs baseline: 2.0671x; 1.4009x over previous
#include <cuda_runtime.h>
#include <cuda_bf16.h>
#include <cstdint>

// Problem dims
#define B_SZ 64
#define T_SZ 512
#define D_SZ 1024
#define R_SZ 1024
#define O_SZ 1024
#define M_SZ (B_SZ * T_SZ)   // 32768

// ---------------- device scratch (static: no runtime allocation) ----------------
__device__ float    g_xh[(size_t)T_SZ * B_SZ * R_SZ];   // [T][B][R]
__device__ float    g_xz[(size_t)T_SZ * B_SZ * R_SZ];   // [T][B][R]
__device__ float    g_Mz[(size_t)R_SZ * R_SZ];          // Wxz @ Whz
__device__ uint32_t g_hx[2][B_SZ * R_SZ];               // packed (bf16 hi | bf16 lo<<16)
__device__ float    g_hf[B_SZ * R_SZ];                  // final h fp32
__device__ unsigned g_arrive;                           // grid barrier counter

// ==================== helpers ====================
__device__ __forceinline__ uint32_t smem_u32(const void* p) {
    uint32_t a;
    asm("{ .reg .u64 t; cvta.to.shared.u64 t, %1; cvt.u32.u64 %0, t; }" : "=r"(a) : "l"(p));
    return a;
}
__device__ __forceinline__ void ldsm_x4(uint32_t r[4], uint32_t addr) {
    asm volatile("ldmatrix.sync.aligned.m8n8.x4.shared.b16 {%0,%1,%2,%3}, [%4];"
                 : "=r"(r[0]), "=r"(r[1]), "=r"(r[2]), "=r"(r[3]) : "r"(addr));
}
__device__ __forceinline__ void mma_bf16(float d[4], const uint32_t a[4],
                                         uint32_t b0, uint32_t b1) {
    asm volatile("mma.sync.aligned.m16n8k16.row.col.f32.bf16.bf16.f32 "
                 "{%0,%1,%2,%3}, {%4,%5,%6,%7}, {%8,%9}, {%0,%1,%2,%3};"
                 : "+f"(d[0]), "+f"(d[1]), "+f"(d[2]), "+f"(d[3])
                 : "r"(a[0]), "r"(a[1]), "r"(a[2]), "r"(a[3]), "r"(b0), "r"(b1));
}
__device__ __forceinline__ uint32_t pack_bf16_split(float v) {
    __nv_bfloat16 h = __float2bfloat16_rn(v);
    float r = v - __bfloat162float(h);
    __nv_bfloat16 l = __float2bfloat16_rn(r);
    return (uint32_t)__bfloat16_as_ushort(h) | ((uint32_t)__bfloat16_as_ushort(l) << 16);
}
__device__ __forceinline__ uint32_t pack2_hi(float a, float b) {
    return (uint32_t)__bfloat16_as_ushort(__float2bfloat16_rn(a))
         | ((uint32_t)__bfloat16_as_ushort(__float2bfloat16_rn(b)) << 16);
}
__device__ __forceinline__ uint32_t pack2_lo(float a, float b) {
    float ra = a - __bfloat162float(__float2bfloat16_rn(a));
    float rb = b - __bfloat162float(__float2bfloat16_rn(b));
    return pack2_hi(ra, rb);
}

// ==================== init: reset per-replay state ====================
__global__ void init_kernel() {
    int i = blockIdx.x * blockDim.x + threadIdx.x;
    if (i < B_SZ * R_SZ) g_hx[0][i] = 0u;
    if (i == 0) g_arrive = 0u;
}

// ==================== Mz = Wxz @ Whz (SIMT fp32, small) ====================
__global__ void __launch_bounds__(256) mz_kernel(const float* __restrict__ Wxz,
                                                 const float* __restrict__ Whz) {
    __shared__ float As[16][68];
    __shared__ float Bs[16][68];
    const int tid = threadIdx.x;
    const int i0 = blockIdx.x * 64;
    const int j0 = blockIdx.y * 64;
    const int tx = tid & 15;
    const int ty = tid >> 4;
    float acc[4][4] = {};

    for (int k0 = 0; k0 < R_SZ; k0 += 16) {
        {
            int row = tid >> 2;
            int c4  = (tid & 3) * 4;
            float4 a = *(const float4*)(Wxz + (size_t)(i0 + row) * R_SZ + k0 + c4);
            As[c4 + 0][row] = a.x; As[c4 + 1][row] = a.y;
            As[c4 + 2][row] = a.z; As[c4 + 3][row] = a.w;
        }
        {
            int kk = tid >> 4;
            int j4 = (tid & 15) * 4;
            float4 b = *(const float4*)(Whz + (size_t)(k0 + kk) * R_SZ + j0 + j4);
            *(float4*)&Bs[kk][j4] = b;
        }
        __syncthreads();
        #pragma unroll
        for (int kk = 0; kk < 16; kk++) {
            float ar[4], br[4];
            *(float4*)ar = *(const float4*)&As[kk][ty * 4];
            *(float4*)br = *(const float4*)&Bs[kk][tx * 4];
            #pragma unroll
            for (int i = 0; i < 4; i++)
                #pragma unroll
                for (int j = 0; j < 4; j++)
                    acc[i][j] = fmaf(ar[i], br[j], acc[i][j]);
        }
        __syncthreads();
    }
    #pragma unroll
    for (int i = 0; i < 4; i++) {
        float4 v = make_float4(acc[i][0], acc[i][1], acc[i][2], acc[i][3]);
        *(float4*)(g_Mz + (size_t)(i0 + ty * 4 + i) * R_SZ + j0 + tx * 4) = v;
    }
}

// ==================== Precompute xh/xz with HMMA (bf16 hi/lo 3-pass) ====================
// C[32768 x 2048] = X @ [Wxh;Wxz]^T + bias, scattered to [T][B][R].
// 128x128 tile, BK=32, 256 threads (8 warps = 2m x 4n), warp tile 64x32.
#define PP_ROW_B 80                          // plane row stride bytes (32+8 bf16)
#define PP_PLANE 10240                       // 128 rows * 80
#define PP_SMEM (8 * PP_PLANE)               // 2 bufs * (A,B) * (hi,lo)

__global__ void __launch_bounds__(256) precompute_mma(
    const float* __restrict__ x,   const float* __restrict__ Wxh,
    const float* __restrict__ Wxz, const float* __restrict__ bh,
    const float* __restrict__ bz) {
    extern __shared__ char psm[];
    const uint32_t sb = smem_u32(psm);
    const int tid = threadIdx.x, warp = tid >> 5, lane = tid & 31;
    const long m_blk = (long)blockIdx.y * 128;
    const int  n_blk = blockIdx.x * 128;

    const float* W; const float* bias; float* dst; int rb;
    if (n_blk < R_SZ) { W = Wxh; bias = bh; dst = g_xh; rb = n_blk; }
    else              { W = Wxz; bias = bz; dst = g_xz; rb = n_blk - R_SZ; }

    const int m0w = (warp & 1) * 64;
    const int n0w = (warp >> 1) * 32;

    float acc[4][4][4];
    #pragma unroll
    for (int a = 0; a < 4; a++)
        #pragma unroll
        for (int b = 0; b < 4; b++)
            #pragma unroll
            for (int c = 0; c < 4; c++) acc[a][b][c] = 0.0f;

    // loader: 1024 float4-items per operand; item -> row=item>>3, c4=(item&7)*4
    float4 pa[4], pb[4];
    #pragma unroll
    for (int i = 0; i < 4; i++) {
        int item = tid + i * 256; int row = item >> 3; int c4 = (item & 7) * 4;
        pa[i] = *(const float4*)(x + (m_blk + row) * (long)D_SZ + c4);
        pb[i] = *(const float4*)(W + (size_t)(rb + row) * D_SZ + c4);
    }

    int buf = 0;
    for (int k0 = 0; k0 < D_SZ; k0 += 32) {
        // store prefetched tile (split hi/lo)
        char* Ah = psm + ((buf * 2 + 0) * 2 + 0) * PP_PLANE;
        char* Al = Ah + PP_PLANE;
        char* Bh = psm + ((buf * 2 + 1) * 2 + 0) * PP_PLANE;
        char* Bl = Bh + PP_PLANE;
        #pragma unroll
        for (int i = 0; i < 4; i++) {
            int item = tid + i * 256; int row = item >> 3; int c4 = (item & 7) * 4;
            uint32_t o = (uint32_t)row * PP_ROW_B + (uint32_t)c4 * 2;
            *(uint32_t*)(Ah + o)     = pack2_hi(pa[i].x, pa[i].y);
            *(uint32_t*)(Ah + o + 4) = pack2_hi(pa[i].z, pa[i].w);
            *(uint32_t*)(Al + o)     = pack2_lo(pa[i].x, pa[i].y);
            *(uint32_t*)(Al + o + 4) = pack2_lo(pa[i].z, pa[i].w);
            *(uint32_t*)(Bh + o)     = pack2_hi(pb[i].x, pb[i].y);
            *(uint32_t*)(Bh + o + 4) = pack2_hi(pb[i].z, pb[i].w);
            *(uint32_t*)(Bl + o)     = pack2_lo(pb[i].x, pb[i].y);
            *(uint32_t*)(Bl + o + 4) = pack2_lo(pb[i].z, pb[i].w);
        }
        __syncthreads();
        // prefetch next k-slab
        if (k0 + 32 < D_SZ) {
            #pragma unroll
            for (int i = 0; i < 4; i++) {
                int item = tid + i * 256; int row = item >> 3; int c4 = (item & 7) * 4;
                pa[i] = *(const float4*)(x + (m_blk + row) * (long)D_SZ + k0 + 32 + c4);
                pb[i] = *(const float4*)(W + (size_t)(rb + row) * D_SZ + k0 + 32 + c4);
            }
        }
        // compute current slab
        const uint32_t AhS = sb + (uint32_t)(((buf * 2 + 0) * 2 + 0) * PP_PLANE);
        const uint32_t AlS = AhS + PP_PLANE;
        #pragma unroll
        for (int k16 = 0; k16 < 2; k16++) {
            uint32_t ahi[4][4], alo[4][4];
            #pragma unroll
            for (int mi = 0; mi < 4; mi++) {
                uint32_t ar = (uint32_t)(m0w + mi * 16 + (lane & 15)) * PP_ROW_B
                            + (uint32_t)(lane >> 4) * 16 + (uint32_t)k16 * 32;
                ldsm_x4(ahi[mi], AhS + ar);
                ldsm_x4(alo[mi], AlS + ar);
            }
            uint32_t bhw[4][2], blw[4][2];
            #pragma unroll
            for (int ni = 0; ni < 4; ni++) {
                uint32_t bo = (uint32_t)(n0w + ni * 8 + (lane >> 2)) * PP_ROW_B
                            + (uint32_t)((lane & 3) * 2) * 2 + (uint32_t)k16 * 32;
                bhw[ni][0] = *(const uint32_t*)(Bh + bo);
                bhw[ni][1] = *(const uint32_t*)(Bh + bo + 16);
                blw[ni][0] = *(const uint32_t*)(Bl + bo);
                blw[ni][1] = *(const uint32_t*)(Bl + bo + 16);
            }
            #pragma unroll
            for (int mi = 0; mi < 4; mi++)
                #pragma unroll
                for (int ni = 0; ni < 4; ni++) {
                    mma_bf16(acc[mi][ni], ahi[mi], bhw[ni][0], bhw[ni][1]);
                    mma_bf16(acc[mi][ni], ahi[mi], blw[ni][0], blw[ni][1]);
                    mma_bf16(acc[mi][ni], alo[mi], bhw[ni][0], bhw[ni][1]);
                }
        }
        __syncthreads();
        buf ^= 1;
    }

    // epilogue: + bias, scatter to [T][B][R]
    #pragma unroll
    for (int ni = 0; ni < 4; ni++) {
        int col = n0w + ni * 8 + (lane & 3) * 2;
        float2 bv = *(const float2*)(bias + rb + col);
        #pragma unroll
        for (int mi = 0; mi < 4; mi++) {
            #pragma unroll
            for (int half = 0; half < 2; half++) {
                long m = m_blk + m0w + mi * 16 + (lane >> 2) + half * 8;
                int b = (int)(m >> 9), t = (int)(m & 511);
                float2 v;
                v.x = acc[mi][ni][half * 2 + 0] + bv.x;
                v.y = acc[mi][ni][half * 2 + 1] + bv.y;
                *(float2*)(dst + ((long)t * B_SZ + b) * R_SZ + rb + col) = v;
            }
        }
    }
}

// ==================== Persistent warp-MMA scan (8 warps) ====================
// 64 CTAs x 256 threads. CTA owns r-slice [cta*16, +16).
// Warp w: m-stripe m0=(w>>1)*16 (16 rows), n-pair njq=(w&1)*8 (h cols njq..+8, z cols 16+njq..).
// KC=128 (8 chunks), ping-pong staged A (h) hi/lo; B weights SMEM-resident bf16 hi/lo.
#define NCTA 64
#define KC 128
#define NCHUNK (R_SZ / KC)                   // 8
#define B_ROW_E 1032
#define B_ROW_BYTES (B_ROW_E * 2)            // 2064
#define A_ROW_BYTES 272                      // (128+8) bf16
#define A_PLANE_SZ (64 * A_ROW_BYTES)        // 17408
#define OFF_BHI 0
#define OFF_BLO (32 * B_ROW_BYTES)           // 66048
#define OFF_A   (2 * 32 * B_ROW_BYTES)       // 132096
#define SCAN_SMEM (OFF_A + 4 * A_PLANE_SZ)   // 201728

__global__ void __launch_bounds__(256) scan_kernel(const float* __restrict__ Whh) {
    extern __shared__ char smem[];
    const uint32_t sbase = smem_u32(smem);
    const int tid  = threadIdx.x;
    const int warp = tid >> 5;
    const int lane = tid & 31;
    const int r_base = blockIdx.x * 16;

    // one-time: weights -> SMEM bf16 hi/lo
    for (int i = tid; i < 32 * R_SZ; i += 256) {
        int j = i >> 10;
        int k = i & 1023;
        float w = (j < 16) ? Whh[(size_t)(r_base + j) * R_SZ + k]
                           : g_Mz[(size_t)(r_base + j - 16) * R_SZ + k];
        __nv_bfloat16 h = __float2bfloat16_rn(w);
        __nv_bfloat16 l = __float2bfloat16_rn(w - __bfloat162float(h));
        *(unsigned short*)(smem + OFF_BHI + j * B_ROW_BYTES + k * 2) = __bfloat16_as_ushort(h);
        *(unsigned short*)(smem + OFF_BLO + j * B_ROW_BYTES + k * 2) = __bfloat16_as_ushort(l);
    }
    __syncthreads();

    const int m0  = (warp >> 1) * 16;
    const int njq = (warp & 1) * 8;

    const int rrow = lane >> 2;
    const int jc   = (lane & 3) * 2;
    const int jg   = r_base + njq + jc;
    const int brow0 = m0 + rrow, brow1 = m0 + rrow + 8;

    const uint32_t b_nh_off = (uint32_t)(njq + rrow) * B_ROW_BYTES + (uint32_t)jc * 2;
    const uint32_t b_nz_off = (uint32_t)(16 + njq + rrow) * B_ROW_BYTES + (uint32_t)jc * 2;
    const uint32_t a_row_off = (uint32_t)(m0 + (lane & 15)) * A_ROW_BYTES + (uint32_t)(lane >> 4) * 16;

    float hold[2][2] = {};

    for (int t = 0; t < T_SZ; t++) {
        float xh[2][2], xz[2][2];
        {
            const float* xh_t = g_xh + (size_t)t * (B_SZ * R_SZ);
            const float* xz_t = g_xz + (size_t)t * (B_SZ * R_SZ);
            float2 a0 = __ldg((const float2*)(xh_t + (size_t)brow0 * R_SZ + jg));
            float2 a1 = __ldg((const float2*)(xh_t + (size_t)brow1 * R_SZ + jg));
            float2 c0 = __ldg((const float2*)(xz_t + (size_t)brow0 * R_SZ + jg));
            float2 c1 = __ldg((const float2*)(xz_t + (size_t)brow1 * R_SZ + jg));
            xh[0][0]=a0.x; xh[0][1]=a0.y; xh[1][0]=a1.x; xh[1][1]=a1.y;
            xz[0][0]=c0.x; xz[0][1]=c0.y; xz[1][0]=c1.x; xz[1][1]=c1.y;
        }

        const uint32_t* hsrc = g_hx[t & 1];

        float d[2][4];
        #pragma unroll
        for (int a = 0; a < 2; a++)
            #pragma unroll
            for (int c = 0; c < 4; c++) d[a][c] = 0.0f;

        // stage chunk 0: 64 rows x 128 cols -> 4096 uint2 items / 256 thr
        #pragma unroll
        for (int it = 0; it < 16; it++) {
            int item = tid + it * 256;
            int b  = item >> 6;
            int kk = (item & 63) * 2;
            uint2 v = __ldcg((const uint2*)(hsrc + (size_t)b * R_SZ + kk));
            uint32_t hp = (v.x & 0xFFFFu) | (v.y << 16);
            uint32_t lp = (v.x >> 16) | (v.y & 0xFFFF0000u);
            uint32_t off = (uint32_t)b * A_ROW_BYTES + (uint32_t)kk * 2;
            *(uint32_t*)(smem + OFF_A + off) = hp;
            *(uint32_t*)(smem + OFF_A + off + A_PLANE_SZ) = lp;
        }
        __syncthreads();

        for (int c = 0; c < NCHUNK; c++) {
            const int cur = c & 1;
            if (c + 1 < NCHUNK) {
                const int nxt = (c + 1) & 1;
                const int rc = (c + 1) * KC;
                #pragma unroll
                for (int it = 0; it < 16; it++) {
                    int item = tid + it * 256;
                    int b  = item >> 6;
                    int kk = (item & 63) * 2;
                    uint2 v = __ldcg((const uint2*)(hsrc + (size_t)b * R_SZ + rc + kk));
                    uint32_t hp = (v.x & 0xFFFFu) | (v.y << 16);
                    uint32_t lp = (v.x >> 16) | (v.y & 0xFFFF0000u);
                    uint32_t off = (uint32_t)(nxt * 2) * A_PLANE_SZ
                                 + (uint32_t)b * A_ROW_BYTES + (uint32_t)kk * 2;
                    *(uint32_t*)(smem + OFF_A + off) = hp;
                    *(uint32_t*)(smem + OFF_A + off + A_PLANE_SZ) = lp;
                }
            }

            const uint32_t a_hi_base = sbase + OFF_A + (uint32_t)(cur * 2) * A_PLANE_SZ;
            const uint32_t a_lo_base = a_hi_base + A_PLANE_SZ;
            const char* bsm = smem;

            #pragma unroll
            for (int kb = 0; kb < KC / 16; kb++) {
                const uint32_t kloc = (uint32_t)kb * 32;
                uint32_t ahi[4], alo[4];
                ldsm_x4(ahi, a_hi_base + a_row_off + kloc);
                ldsm_x4(alo, a_lo_base + a_row_off + kloc);

                uint32_t kB = (uint32_t)(c * KC) * 2 + kloc;
                uint32_t bh0h = *(const uint32_t*)(bsm + OFF_BHI + b_nh_off + kB);
                uint32_t bh1h = *(const uint32_t*)(bsm + OFF_BHI + b_nh_off + kB + 16);
                uint32_t bh0z = *(const uint32_t*)(bsm + OFF_BHI + b_nz_off + kB);
                uint32_t bh1z = *(const uint32_t*)(bsm + OFF_BHI + b_nz_off + kB + 16);
                uint32_t bl0h = *(const uint32_t*)(bsm + OFF_BLO + b_nh_off + kB);
                uint32_t bl1h = *(const uint32_t*)(bsm + OFF_BLO + b_nh_off + kB + 16);
                uint32_t bl0z = *(const uint32_t*)(bsm + OFF_BLO + b_nz_off + kB);
                uint32_t bl1z = *(const uint32_t*)(bsm + OFF_BLO + b_nz_off + kB + 16);

                mma_bf16(d[0], ahi, bh0h, bh1h);
                mma_bf16(d[0], ahi, bl0h, bl1h);
                mma_bf16(d[0], alo, bh0h, bh1h);
                mma_bf16(d[1], ahi, bh0z, bh1z);
                mma_bf16(d[1], ahi, bl0z, bl1z);
                mma_bf16(d[1], alo, bh0z, bh1z);
            }
            __syncthreads();
        }

        // gate epilogue: thread owns 2 rows x 2 cols
        uint32_t* hdst = g_hx[(t + 1) & 1];
        #pragma unroll
        for (int q = 0; q < 2; q++) {
            int br = (q == 0) ? brow0 : brow1;
            uint32_t pk[2];
            #pragma unroll
            for (int cc = 0; cc < 2; cc++) {
                float pre_h = d[0][q * 2 + cc] + xh[q][cc];
                float pre_z = d[1][q * 2 + cc] + xz[q][cc];
                float z  = 1.0f / (1.0f + expf(-pre_z));
                float hb = fmaxf(pre_h, 0.0f);
                float hn = z * hold[q][cc] + (1.0f - z) * hb;
                hold[q][cc] = hn;
                pk[cc] = pack_bf16_split(hn);
            }
            *(uint2*)(hdst + (size_t)br * R_SZ + jg) = make_uint2(pk[0], pk[1]);
            if (t == T_SZ - 1) {
                g_hf[(size_t)br * R_SZ + jg]     = hold[q][0];
                g_hf[(size_t)br * R_SZ + jg + 1] = hold[q][1];
            }
        }

        // grid barrier over 64 CTAs
        __threadfence();
        __syncthreads();
        if (tid == 0) {
            atomicAdd(&g_arrive, 1u);
            unsigned target = (unsigned)NCTA * (unsigned)(t + 1);
            while (*((volatile unsigned*)&g_arrive) < target) { }
            __threadfence();
        }
        __syncthreads();
    }
}

// ==================== Output: y = h_final @ Wy^T + by ====================
__global__ void __launch_bounds__(128) output_kernel(const float* __restrict__ Wy,
                                                     const float* __restrict__ by,
                                                     float* __restrict__ out) {
    __shared__ float shh[R_SZ];
    const int b = blockIdx.x;
    const int o = blockIdx.y * 128 + threadIdx.x;
    const float* hrow = g_hf + (size_t)b * R_SZ;
    #pragma unroll
    for (int v = 0; v < 2; v++) {
        int i4 = threadIdx.x + v * 128;
        ((float4*)shh)[i4] = *(const float4*)(hrow + i4 * 4);
    }
    __syncthreads();
    float acc = __ldg(&by[o]);
    const float* wrow = Wy + (size_t)o * R_SZ;
    #pragma unroll 8
    for (int k4 = 0; k4 < R_SZ / 4; k4++) {
        float4 h4 = ((const float4*)shh)[k4];
        float4 w4 = __ldg((const float4*)(wrow + k4 * 4));
        acc = fmaf(h4.x, w4.x, acc); acc = fmaf(h4.y, w4.y, acc);
        acc = fmaf(h4.z, w4.z, acc); acc = fmaf(h4.w, w4.w, acc);
    }
    out[(size_t)b * O_SZ + o] = acc;
}

// ==================== launch ====================
extern "C" void kernel_launch(void* const* d_in, const int* in_sizes, int n_in,
                              void* d_out, int out_size) {
    const float* x   = (const float*)d_in[0];
    const float* Wxh = (const float*)d_in[1];
    const float* bh  = (const float*)d_in[2];
    const float* Whh = (const float*)d_in[3];
    const float* Wxz = (const float*)d_in[4];
    const float* bz  = (const float*)d_in[5];
    const float* Whz = (const float*)d_in[6];
    const float* Wy  = (const float*)d_in[7];
    const float* by  = (const float*)d_in[8];
    float* out = (float*)d_out;

    static bool attr_set = false;
    if (!attr_set) {
        cudaFuncSetAttribute(scan_kernel,
                             cudaFuncAttributeMaxDynamicSharedMemorySize, SCAN_SMEM);
        cudaFuncSetAttribute(precompute_mma,
                             cudaFuncAttributeMaxDynamicSharedMemorySize, PP_SMEM);
        attr_set = true;
    }

    mz_kernel<<<dim3(R_SZ / 64, R_SZ / 64), 256>>>(Wxz, Whz);
    // n fastest (x), m slower (y): X rows shared across n-tiles within a wave (L2 reuse)
    precompute_mma<<<dim3(2048 / 128, M_SZ / 128), 256, PP_SMEM>>>(x, Wxh, Wxz, bh, bz);
    init_kernel<<<(B_SZ * R_SZ + 255) / 256, 256>>>();
    scan_kernel<<<NCTA, 256, SCAN_SMEM>>>(Whh);
    output_kernel<<<dim3(B_SZ, O_SZ / 128), 128>>>(Wy, by, out);
}

// round 7
// speedup vs baseline: 2.3046x; 1.1149x over previous
#include <cuda_runtime.h>
#include <cuda_bf16.h>
#include <cstdint>

// Problem dims
#define B_SZ 64
#define T_SZ 512
#define D_SZ 1024
#define R_SZ 1024
#define O_SZ 1024
#define M_SZ (B_SZ * T_SZ)   // 32768

// ---------------- device scratch (static: no runtime allocation) ----------------
__device__ float          g_xh[(size_t)T_SZ * B_SZ * R_SZ];   // [T][B][R]
__device__ float          g_xz[(size_t)T_SZ * B_SZ * R_SZ];   // [T][B][R]
__device__ float          g_Mz[(size_t)R_SZ * R_SZ];          // Wxz @ Whz
__device__ unsigned short g_x_hi[(size_t)M_SZ * D_SZ];        // X bf16 hi
__device__ unsigned short g_x_lo[(size_t)M_SZ * D_SZ];        // X bf16 lo
__device__ unsigned short g_w_hi[(size_t)2048 * D_SZ];        // [Wxh;Wxz] bf16 hi
__device__ unsigned short g_w_lo[(size_t)2048 * D_SZ];        // [Wxh;Wxz] bf16 lo
__device__ unsigned short g_h_hi[2][B_SZ * R_SZ];             // h bf16 hi (dbl buf)
__device__ unsigned short g_h_lo[2][B_SZ * R_SZ];             // h bf16 lo
__device__ float          g_hf[B_SZ * R_SZ];                  // final h fp32
__device__ unsigned       g_arrive;                           // grid barrier counter

// ==================== helpers ====================
__device__ __forceinline__ uint32_t smem_u32(const void* p) {
    uint32_t a;
    asm("{ .reg .u64 t; cvta.to.shared.u64 t, %1; cvt.u32.u64 %0, t; }" : "=r"(a) : "l"(p));
    return a;
}
__device__ __forceinline__ void ldsm_x4(uint32_t r[4], uint32_t addr) {
    asm volatile("ldmatrix.sync.aligned.m8n8.x4.shared.b16 {%0,%1,%2,%3}, [%4];"
                 : "=r"(r[0]), "=r"(r[1]), "=r"(r[2]), "=r"(r[3]) : "r"(addr));
}
__device__ __forceinline__ void mma_bf16(float d[4], const uint32_t a[4],
                                         uint32_t b0, uint32_t b1) {
    asm volatile("mma.sync.aligned.m16n8k16.row.col.f32.bf16.bf16.f32 "
                 "{%0,%1,%2,%3}, {%4,%5,%6,%7}, {%8,%9}, {%0,%1,%2,%3};"
                 : "+f"(d[0]), "+f"(d[1]), "+f"(d[2]), "+f"(d[3])
                 : "r"(a[0]), "r"(a[1]), "r"(a[2]), "r"(a[3]), "r"(b0), "r"(b1));
}
__device__ __forceinline__ void cp_async16(uint32_t dst, const void* src) {
    asm volatile("cp.async.cg.shared.global [%0], [%1], 16;" :: "r"(dst), "l"(src));
}
#define CP_COMMIT() asm volatile("cp.async.commit_group;" ::: "memory")
#define CP_WAIT0()  asm volatile("cp.async.wait_group 0;" ::: "memory")
#define CP_WAIT1()  asm volatile("cp.async.wait_group 1;" ::: "memory")

__device__ __forceinline__ uint32_t pack2_hi(float a, float b) {
    return (uint32_t)__bfloat16_as_ushort(__float2bfloat16_rn(a))
         | ((uint32_t)__bfloat16_as_ushort(__float2bfloat16_rn(b)) << 16);
}
__device__ __forceinline__ uint32_t pack2_lo(float a, float b) {
    float ra = a - __bfloat162float(__float2bfloat16_rn(a));
    float rb = b - __bfloat162float(__float2bfloat16_rn(b));
    return pack2_hi(ra, rb);
}

// ==================== init ====================
__global__ void init_kernel() {
    int i = blockIdx.x * blockDim.x + threadIdx.x;
    if (i < B_SZ * R_SZ) { g_h_hi[0][i] = 0; g_h_lo[0][i] = 0; }
    if (i == 0) g_arrive = 0u;
}

// ==================== fp32 -> bf16 hi/lo split (n divisible by 1024) ====================
__global__ void __launch_bounds__(256) split_kernel(const float* __restrict__ src,
                                                    unsigned short* __restrict__ hi,
                                                    unsigned short* __restrict__ lo) {
    size_t i = ((size_t)blockIdx.x * 256 + threadIdx.x) * 4;
    float4 v = *(const float4*)(src + i);
    uint2 h, l;
    h.x = pack2_hi(v.x, v.y); h.y = pack2_hi(v.z, v.w);
    l.x = pack2_lo(v.x, v.y); l.y = pack2_lo(v.z, v.w);
    *(uint2*)(hi + i) = h;
    *(uint2*)(lo + i) = l;
}

// ==================== Mz = Wxz @ Whz (SIMT fp32) ====================
__global__ void __launch_bounds__(256) mz_kernel(const float* __restrict__ Wxz,
                                                 const float* __restrict__ Whz) {
    __shared__ float As[16][68];
    __shared__ float Bs[16][68];
    const int tid = threadIdx.x;
    const int i0 = blockIdx.x * 64;
    const int j0 = blockIdx.y * 64;
    const int tx = tid & 15;
    const int ty = tid >> 4;
    float acc[4][4] = {};

    for (int k0 = 0; k0 < R_SZ; k0 += 16) {
        {
            int row = tid >> 2;
            int c4  = (tid & 3) * 4;
            float4 a = *(const float4*)(Wxz + (size_t)(i0 + row) * R_SZ + k0 + c4);
            As[c4 + 0][row] = a.x; As[c4 + 1][row] = a.y;
            As[c4 + 2][row] = a.z; As[c4 + 3][row] = a.w;
        }
        {
            int kk = tid >> 4;
            int j4 = (tid & 15) * 4;
            float4 b = *(const float4*)(Whz + (size_t)(k0 + kk) * R_SZ + j0 + j4);
            *(float4*)&Bs[kk][j4] = b;
        }
        __syncthreads();
        #pragma unroll
        for (int kk = 0; kk < 16; kk++) {
            float ar[4], br[4];
            *(float4*)ar = *(const float4*)&As[kk][ty * 4];
            *(float4*)br = *(const float4*)&Bs[kk][tx * 4];
            #pragma unroll
            for (int i = 0; i < 4; i++)
                #pragma unroll
                for (int j = 0; j < 4; j++)
                    acc[i][j] = fmaf(ar[i], br[j], acc[i][j]);
        }
        __syncthreads();
    }
    #pragma unroll
    for (int i = 0; i < 4; i++) {
        float4 v = make_float4(acc[i][0], acc[i][1], acc[i][2], acc[i][3]);
        *(float4*)(g_Mz + (size_t)(i0 + ty * 4 + i) * R_SZ + j0 + tx * 4) = v;
    }
}

// ==================== Precompute xh/xz with HMMA + cp.async (pre-split inputs) ====================
// 128x128 tile, BK=32, 256 threads (8 warps = 2m x 4n), warp tile 64x32.
#define PP_ROW_B 80                          // plane row stride bytes (32+8 bf16)
#define PP_PLANE 10240                       // 128 rows * 80
#define PP_SMEM (8 * PP_PLANE)               // 2 bufs * 4 planes (Ahi,Alo,Bhi,Blo)

__global__ void __launch_bounds__(256) precompute_mma(const float* __restrict__ bh,
                                                      const float* __restrict__ bz) {
    extern __shared__ char psm[];
    const uint32_t sb = smem_u32(psm);
    const int tid = threadIdx.x, warp = tid >> 5, lane = tid & 31;
    const long m_blk = (long)blockIdx.y * 128;
    const int  n_blk = blockIdx.x * 128;

    const float* bias; float* dst; int rb;
    if (n_blk < R_SZ) { bias = bh; dst = g_xh; rb = n_blk; }
    else              { bias = bz; dst = g_xz; rb = n_blk - R_SZ; }

    const int m0w = (warp & 1) * 64;
    const int n0w = (warp >> 1) * 32;

    float acc[4][4][4];
    #pragma unroll
    for (int a = 0; a < 4; a++)
        #pragma unroll
        for (int b = 0; b < 4; b++)
            #pragma unroll
            for (int c = 0; c < 4; c++) acc[a][b][c] = 0.0f;

    // stage one 32-wide K slab into buffer `buf` via cp.async (4 planes)
    auto stage = [&](int buf, int k0) {
        #pragma unroll
        for (int r = 0; r < 2; r++) {
            int cid = tid + r * 256;          // 0..511
            int row = cid >> 2;               // 0..127
            int qt  = cid & 3;                // 16B quarter
            uint32_t dA = sb + (uint32_t)((buf * 4 + 0) * PP_PLANE) + (uint32_t)row * PP_ROW_B + (uint32_t)qt * 16;
            uint32_t dB = sb + (uint32_t)((buf * 4 + 2) * PP_PLANE) + (uint32_t)row * PP_ROW_B + (uint32_t)qt * 16;
            size_t sa = (size_t)(m_blk + row) * D_SZ + k0 + qt * 8;
            size_t sw = (size_t)(n_blk + row) * D_SZ + k0 + qt * 8;
            cp_async16(dA,              g_x_hi + sa);
            cp_async16(dA + PP_PLANE,   g_x_lo + sa);
            cp_async16(dB,              g_w_hi + sw);
            cp_async16(dB + PP_PLANE,   g_w_lo + sw);
        }
    };

    int buf = 0;
    stage(0, 0);
    CP_COMMIT();
    for (int s = 0; s < D_SZ / 32; s++) {
        if (s + 1 < D_SZ / 32) { stage(buf ^ 1, (s + 1) * 32); CP_COMMIT(); CP_WAIT1(); }
        else                   { CP_WAIT0(); }
        __syncthreads();

        const uint32_t AhS = sb + (uint32_t)((buf * 4 + 0) * PP_PLANE);
        const uint32_t AlS = AhS + PP_PLANE;
        const char* Bh = psm + (buf * 4 + 2) * PP_PLANE;
        const char* Bl = Bh + PP_PLANE;
        #pragma unroll
        for (int k16 = 0; k16 < 2; k16++) {
            uint32_t ahi[4][4], alo[4][4];
            #pragma unroll
            for (int mi = 0; mi < 4; mi++) {
                uint32_t ar = (uint32_t)(m0w + mi * 16 + (lane & 15)) * PP_ROW_B
                            + (uint32_t)(lane >> 4) * 16 + (uint32_t)k16 * 32;
                ldsm_x4(ahi[mi], AhS + ar);
                ldsm_x4(alo[mi], AlS + ar);
            }
            uint32_t bhw[4][2], blw[4][2];
            #pragma unroll
            for (int ni = 0; ni < 4; ni++) {
                uint32_t bo = (uint32_t)(n0w + ni * 8 + (lane >> 2)) * PP_ROW_B
                            + (uint32_t)((lane & 3) * 2) * 2 + (uint32_t)k16 * 32;
                bhw[ni][0] = *(const uint32_t*)(Bh + bo);
                bhw[ni][1] = *(const uint32_t*)(Bh + bo + 16);
                blw[ni][0] = *(const uint32_t*)(Bl + bo);
                blw[ni][1] = *(const uint32_t*)(Bl + bo + 16);
            }
            #pragma unroll
            for (int mi = 0; mi < 4; mi++)
                #pragma unroll
                for (int ni = 0; ni < 4; ni++) {
                    mma_bf16(acc[mi][ni], ahi[mi], bhw[ni][0], bhw[ni][1]);
                    mma_bf16(acc[mi][ni], ahi[mi], blw[ni][0], blw[ni][1]);
                    mma_bf16(acc[mi][ni], alo[mi], bhw[ni][0], bhw[ni][1]);
                }
        }
        __syncthreads();
        buf ^= 1;
    }

    // epilogue: + bias, scatter to [T][B][R]
    #pragma unroll
    for (int ni = 0; ni < 4; ni++) {
        int col = n0w + ni * 8 + (lane & 3) * 2;
        float2 bv = *(const float2*)(bias + rb + col);
        #pragma unroll
        for (int mi = 0; mi < 4; mi++) {
            #pragma unroll
            for (int half = 0; half < 2; half++) {
                long m = m_blk + m0w + mi * 16 + (lane >> 2) + half * 8;
                int b = (int)(m >> 9), t = (int)(m & 511);
                float2 v;
                v.x = acc[mi][ni][half * 2 + 0] + bv.x;
                v.y = acc[mi][ni][half * 2 + 1] + bv.y;
                *(float2*)(dst + ((long)t * B_SZ + b) * R_SZ + rb + col) = v;
            }
        }
    }
}

// ==================== Persistent warp-MMA scan (16 warps) ====================
// 64 CTAs x 512 threads. CTA owns r-slice [cta*16, +16).
// B (SMEM): 32 rows = [Whh(16); Mz(16)], bf16 hi+lo. D[64x32] per step.
// Warp w: m-stripe (w>>2)*16, n-tile q=w&3 (q<2: h-cols q*8.., q>=2: z-cols (q-2)*8..).
// z-warps push sigmoid(z) through SMEM zbuf; h-warps gate (h_old in registers).
#define NCTA 64
#define KC 128
#define NCHUNK (R_SZ / KC)                   // 8
#define B_ROW_BYTES 2064                     // (1024+8) bf16
#define A_ROW_BYTES 272                      // (128+8) bf16
#define A_PLANE_SZ (64 * A_ROW_BYTES)        // 17408
#define OFF_BHI 0
#define OFF_BLO (32 * B_ROW_BYTES)           // 66048
#define OFF_A   (2 * 32 * B_ROW_BYTES)       // 132096
#define OFF_Z   (OFF_A + 4 * A_PLANE_SZ)     // 201728
#define Z_STRIDE 18
#define SCAN_SMEM (OFF_Z + 64 * Z_STRIDE * 4)  // 206336

__global__ void __launch_bounds__(512) scan_kernel(const float* __restrict__ Whh) {
    extern __shared__ char smem[];
    const uint32_t sbase = smem_u32(smem);
    float* zbuf = (float*)(smem + OFF_Z);
    const int tid  = threadIdx.x;
    const int warp = tid >> 5;
    const int lane = tid & 31;
    const int r_base = blockIdx.x * 16;

    // one-time: weights -> SMEM bf16 hi/lo
    for (int i = tid; i < 32 * R_SZ; i += 512) {
        int j = i >> 10;
        int k = i & 1023;
        float w = (j < 16) ? Whh[(size_t)(r_base + j) * R_SZ + k]
                           : g_Mz[(size_t)(r_base + j - 16) * R_SZ + k];
        __nv_bfloat16 h = __float2bfloat16_rn(w);
        __nv_bfloat16 l = __float2bfloat16_rn(w - __bfloat162float(h));
        *(unsigned short*)(smem + OFF_BHI + j * B_ROW_BYTES + k * 2) = __bfloat16_as_ushort(h);
        *(unsigned short*)(smem + OFF_BLO + j * B_ROW_BYTES + k * 2) = __bfloat16_as_ushort(l);
    }
    __syncthreads();

    const int m0 = (warp >> 2) * 16;         // m-stripe
    const int q  = warp & 3;                 // n-tile (0,1=h; 2,3=z)
    const bool is_h = (q < 2);

    const int rrow = lane >> 2;              // 0..7
    const int jc   = (lane & 3) * 2;         // 0,2,4,6
    const int rc   = (q & 1) * 8 + jc;       // r-col within 16-slice
    const int jg   = r_base + rc;            // global r
    const int brow0 = m0 + rrow, brow1 = brow0 + 8;

    const uint32_t b_off = (uint32_t)(q * 8 + rrow) * B_ROW_BYTES + (uint32_t)jc * 2;
    const uint32_t a_row_off = (uint32_t)(m0 + (lane & 15)) * A_ROW_BYTES + (uint32_t)(lane >> 4) * 16;

    float hold[2][2] = {};

    for (int t = 0; t < T_SZ; t++) {
        // prefetch per-step inputs for owned elements
        float xv[2][2];
        {
            const float* src = (is_h ? g_xh : g_xz) + (size_t)t * (B_SZ * R_SZ);
            float2 a0 = __ldg((const float2*)(src + (size_t)brow0 * R_SZ + jg));
            float2 a1 = __ldg((const float2*)(src + (size_t)brow1 * R_SZ + jg));
            xv[0][0] = a0.x; xv[0][1] = a0.y; xv[1][0] = a1.x; xv[1][1] = a1.y;
        }

        const unsigned short* hhi = g_h_hi[t & 1];
        const unsigned short* hlo = g_h_lo[t & 1];

        float d[4] = {0.0f, 0.0f, 0.0f, 0.0f};

        // stage chunk 0: 64 rows x 128 cols per plane (1024 16B chunks / plane)
        auto stage = [&](int buf, int kc) {
            #pragma unroll
            for (int r = 0; r < 2; r++) {
                int cid = tid + r * 512;          // 0..1023
                int row = cid >> 4;               // 0..63
                int c16 = cid & 15;
                uint32_t dA = sbase + OFF_A + (uint32_t)(buf * 2) * A_PLANE_SZ
                            + (uint32_t)row * A_ROW_BYTES + (uint32_t)c16 * 16;
                size_t s = (size_t)row * R_SZ + kc + c16 * 8;
                cp_async16(dA,              hhi + s);
                cp_async16(dA + A_PLANE_SZ, hlo + s);
            }
        };

        int buf = 0;
        stage(0, 0);
        CP_COMMIT();
        for (int c = 0; c < NCHUNK; c++) {
            if (c + 1 < NCHUNK) { stage(buf ^ 1, (c + 1) * KC); CP_COMMIT(); CP_WAIT1(); }
            else                { CP_WAIT0(); }
            __syncthreads();

            const uint32_t a_hi_base = sbase + OFF_A + (uint32_t)(buf * 2) * A_PLANE_SZ;
            const uint32_t a_lo_base = a_hi_base + A_PLANE_SZ;
            const char* bsm = smem;

            #pragma unroll
            for (int kb = 0; kb < KC / 16; kb++) {
                const uint32_t kloc = (uint32_t)kb * 32;
                uint32_t ahi[4], alo[4];
                ldsm_x4(ahi, a_hi_base + a_row_off + kloc);
                ldsm_x4(alo, a_lo_base + a_row_off + kloc);

                uint32_t kB = (uint32_t)(c * KC) * 2 + kloc;
                uint32_t b0h = *(const uint32_t*)(bsm + OFF_BHI + b_off + kB);
                uint32_t b1h = *(const uint32_t*)(bsm + OFF_BHI + b_off + kB + 16);
                uint32_t b0l = *(const uint32_t*)(bsm + OFF_BLO + b_off + kB);
                uint32_t b1l = *(const uint32_t*)(bsm + OFF_BLO + b_off + kB + 16);

                mma_bf16(d, ahi, b0h, b1h);
                mma_bf16(d, ahi, b0l, b1l);
                mma_bf16(d, alo, b0h, b1h);
            }
            __syncthreads();
            buf ^= 1;
        }

        // z-warps: sigmoid -> zbuf
        if (!is_h) {
            #pragma unroll
            for (int qq = 0; qq < 2; qq++) {
                int br = (qq == 0) ? brow0 : brow1;
                float2 zv;
                zv.x = 1.0f / (1.0f + expf(-(d[qq * 2 + 0] + xv[qq][0])));
                zv.y = 1.0f / (1.0f + expf(-(d[qq * 2 + 1] + xv[qq][1])));
                *(float2*)&zbuf[br * Z_STRIDE + rc] = zv;
            }
        }
        __syncthreads();
        // h-warps: gate + write h
        if (is_h) {
            unsigned short* dhi = g_h_hi[(t + 1) & 1];
            unsigned short* dlo = g_h_lo[(t + 1) & 1];
            #pragma unroll
            for (int qq = 0; qq < 2; qq++) {
                int br = (qq == 0) ? brow0 : brow1;
                float2 zv = *(const float2*)&zbuf[br * Z_STRIDE + rc];
                float hb0 = fmaxf(d[qq * 2 + 0] + xv[qq][0], 0.0f);
                float hb1 = fmaxf(d[qq * 2 + 1] + xv[qq][1], 0.0f);
                float hn0 = zv.x * hold[qq][0] + (1.0f - zv.x) * hb0;
                float hn1 = zv.y * hold[qq][1] + (1.0f - zv.y) * hb1;
                hold[qq][0] = hn0; hold[qq][1] = hn1;
                size_t o = (size_t)br * R_SZ + jg;
                *(uint32_t*)(dhi + o) = pack2_hi(hn0, hn1);
                *(uint32_t*)(dlo + o) = pack2_lo(hn0, hn1);
                if (t == T_SZ - 1) {
                    g_hf[o] = hn0; g_hf[o + 1] = hn1;
                }
            }
        }

        // grid barrier over 64 CTAs
        __threadfence();
        __syncthreads();
        if (tid == 0) {
            atomicAdd(&g_arrive, 1u);
            unsigned target = (unsigned)NCTA * (unsigned)(t + 1);
            while (*((volatile unsigned*)&g_arrive) < target) { }
            __threadfence();
        }
        __syncthreads();
    }
}

// ==================== Output: y = h_final @ Wy^T + by ====================
__global__ void __launch_bounds__(128) output_kernel(const float* __restrict__ Wy,
                                                     const float* __restrict__ by,
                                                     float* __restrict__ out) {
    __shared__ float shh[R_SZ];
    const int b = blockIdx.x;
    const int o = blockIdx.y * 128 + threadIdx.x;
    const float* hrow = g_hf + (size_t)b * R_SZ;
    #pragma unroll
    for (int v = 0; v < 2; v++) {
        int i4 = threadIdx.x + v * 128;
        ((float4*)shh)[i4] = *(const float4*)(hrow + i4 * 4);
    }
    __syncthreads();
    float acc = __ldg(&by[o]);
    const float* wrow = Wy + (size_t)o * R_SZ;
    #pragma unroll 8
    for (int k4 = 0; k4 < R_SZ / 4; k4++) {
        float4 h4 = ((const float4*)shh)[k4];
        float4 w4 = __ldg((const float4*)(wrow + k4 * 4));
        acc = fmaf(h4.x, w4.x, acc); acc = fmaf(h4.y, w4.y, acc);
        acc = fmaf(h4.z, w4.z, acc); acc = fmaf(h4.w, w4.w, acc);
    }
    out[(size_t)b * O_SZ + o] = acc;
}

// ==================== launch ====================
extern "C" void kernel_launch(void* const* d_in, const int* in_sizes, int n_in,
                              void* d_out, int out_size) {
    const float* x   = (const float*)d_in[0];
    const float* Wxh = (const float*)d_in[1];
    const float* bh  = (const float*)d_in[2];
    const float* Whh = (const float*)d_in[3];
    const float* Wxz = (const float*)d_in[4];
    const float* bz  = (const float*)d_in[5];
    const float* Whz = (const float*)d_in[6];
    const float* Wy  = (const float*)d_in[7];
    const float* by  = (const float*)d_in[8];
    float* out = (float*)d_out;

    static bool attr_set = false;
    if (!attr_set) {
        cudaFuncSetAttribute(scan_kernel,
                             cudaFuncAttributeMaxDynamicSharedMemorySize, SCAN_SMEM);
        cudaFuncSetAttribute(precompute_mma,
                             cudaFuncAttributeMaxDynamicSharedMemorySize, PP_SMEM);
        attr_set = true;
    }

    // split X and stacked W into bf16 hi/lo planes
    unsigned short *xhi_p, *xlo_p, *whi_p, *wlo_p;
    cudaGetSymbolAddress((void**)&xhi_p, g_x_hi);
    cudaGetSymbolAddress((void**)&xlo_p, g_x_lo);
    cudaGetSymbolAddress((void**)&whi_p, g_w_hi);
    cudaGetSymbolAddress((void**)&wlo_p, g_w_lo);
    split_kernel<<<(int)((size_t)M_SZ * D_SZ / 1024), 256>>>(x, xhi_p, xlo_p);
    split_kernel<<<(R_SZ * D_SZ) / 1024, 256>>>(Wxh, whi_p, wlo_p);
    split_kernel<<<(R_SZ * D_SZ) / 1024, 256>>>(Wxz, whi_p + (size_t)R_SZ * D_SZ,
                                                wlo_p + (size_t)R_SZ * D_SZ);

    mz_kernel<<<dim3(R_SZ / 64, R_SZ / 64), 256>>>(Wxz, Whz);
    // n fastest (x): W tiles reused across m within a wave; X L2-resident per wave
    precompute_mma<<<dim3(2048 / 128, M_SZ / 128), 256, PP_SMEM>>>(bh, bz);
    init_kernel<<<(B_SZ * R_SZ + 255) / 256, 256>>>();
    scan_kernel<<<NCTA, 512, SCAN_SMEM>>>(Whh);
    output_kernel<<<dim3(B_SZ, O_SZ / 128), 128>>>(Wy, by, out);
}

// round 8
// speedup vs baseline: 2.4702x; 1.0719x over previous
#include <cuda_runtime.h>
#include <cuda_bf16.h>
#include <cstdint>

// Problem dims
#define B_SZ 64
#define T_SZ 512
#define D_SZ 1024
#define R_SZ 1024
#define O_SZ 1024
#define M_SZ (B_SZ * T_SZ)   // 32768

// ---------------- device scratch (static: no runtime allocation) ----------------
__device__ float          g_xh[(size_t)T_SZ * B_SZ * R_SZ];   // [T][B][R]
__device__ float          g_xz[(size_t)T_SZ * B_SZ * R_SZ];   // [T][B][R]
__device__ float          g_Mz[(size_t)R_SZ * R_SZ];          // Wxz @ Whz
__device__ unsigned short g_x_hi[(size_t)M_SZ * D_SZ];        // X bf16 hi
__device__ unsigned short g_x_lo[(size_t)M_SZ * D_SZ];        // X bf16 lo
__device__ unsigned short g_w_hi[(size_t)2048 * D_SZ];        // [Wxh;Wxz] bf16 hi
__device__ unsigned short g_w_lo[(size_t)2048 * D_SZ];        // [Wxh;Wxz] bf16 lo
__device__ unsigned short g_h_hi[2][B_SZ * R_SZ];             // h bf16 hi (dbl buf)
__device__ unsigned short g_h_lo[2][B_SZ * R_SZ];             // h bf16 lo
__device__ float          g_hf[B_SZ * R_SZ];                  // final h fp32
__device__ unsigned       g_arrive;                           // grid barrier counter

// ==================== helpers ====================
__device__ __forceinline__ uint32_t smem_u32(const void* p) {
    uint32_t a;
    asm("{ .reg .u64 t; cvta.to.shared.u64 t, %1; cvt.u32.u64 %0, t; }" : "=r"(a) : "l"(p));
    return a;
}
__device__ __forceinline__ void ldsm_x4(uint32_t r[4], uint32_t addr) {
    asm volatile("ldmatrix.sync.aligned.m8n8.x4.shared.b16 {%0,%1,%2,%3}, [%4];"
                 : "=r"(r[0]), "=r"(r[1]), "=r"(r[2]), "=r"(r[3]) : "r"(addr));
}
__device__ __forceinline__ void mma_bf16(float d[4], const uint32_t a[4],
                                         uint32_t b0, uint32_t b1) {
    asm volatile("mma.sync.aligned.m16n8k16.row.col.f32.bf16.bf16.f32 "
                 "{%0,%1,%2,%3}, {%4,%5,%6,%7}, {%8,%9}, {%0,%1,%2,%3};"
                 : "+f"(d[0]), "+f"(d[1]), "+f"(d[2]), "+f"(d[3])
                 : "r"(a[0]), "r"(a[1]), "r"(a[2]), "r"(a[3]), "r"(b0), "r"(b1));
}
__device__ __forceinline__ void cp_async16(uint32_t dst, const void* src) {
    asm volatile("cp.async.cg.shared.global [%0], [%1], 16;" :: "r"(dst), "l"(src));
}
#define CP_COMMIT() asm volatile("cp.async.commit_group;" ::: "memory")
#define CP_WAIT0()  asm volatile("cp.async.wait_group 0;" ::: "memory")
#define CP_WAIT1()  asm volatile("cp.async.wait_group 1;" ::: "memory")
#define BAR_SYNC(id, cnt) asm volatile("bar.sync %0, %1;" :: "r"(id), "r"(cnt) : "memory")

__device__ __forceinline__ uint32_t pack2_hi(float a, float b) {
    return (uint32_t)__bfloat16_as_ushort(__float2bfloat16_rn(a))
         | ((uint32_t)__bfloat16_as_ushort(__float2bfloat16_rn(b)) << 16);
}
__device__ __forceinline__ uint32_t pack2_lo(float a, float b) {
    float ra = a - __bfloat162float(__float2bfloat16_rn(a));
    float rb = b - __bfloat162float(__float2bfloat16_rn(b));
    return pack2_hi(ra, rb);
}

// ==================== init ====================
__global__ void init_kernel() {
    int i = blockIdx.x * blockDim.x + threadIdx.x;
    if (i < B_SZ * R_SZ) { g_h_hi[0][i] = 0; g_h_lo[0][i] = 0; }
    if (i == 0) g_arrive = 0u;
}

// ==================== fp32 -> bf16 hi/lo split ====================
__global__ void __launch_bounds__(256) split_kernel(const float* __restrict__ src,
                                                    unsigned short* __restrict__ hi,
                                                    unsigned short* __restrict__ lo) {
    size_t i = ((size_t)blockIdx.x * 256 + threadIdx.x) * 4;
    float4 v = *(const float4*)(src + i);
    uint2 h, l;
    h.x = pack2_hi(v.x, v.y); h.y = pack2_hi(v.z, v.w);
    l.x = pack2_lo(v.x, v.y); l.y = pack2_lo(v.z, v.w);
    *(uint2*)(hi + i) = h;
    *(uint2*)(lo + i) = l;
}

// ==================== Mz = Wxz @ Whz (SIMT fp32) ====================
__global__ void __launch_bounds__(256) mz_kernel(const float* __restrict__ Wxz,
                                                 const float* __restrict__ Whz) {
    __shared__ float As[16][68];
    __shared__ float Bs[16][68];
    const int tid = threadIdx.x;
    const int i0 = blockIdx.x * 64;
    const int j0 = blockIdx.y * 64;
    const int tx = tid & 15;
    const int ty = tid >> 4;
    float acc[4][4] = {};

    for (int k0 = 0; k0 < R_SZ; k0 += 16) {
        {
            int row = tid >> 2;
            int c4  = (tid & 3) * 4;
            float4 a = *(const float4*)(Wxz + (size_t)(i0 + row) * R_SZ + k0 + c4);
            As[c4 + 0][row] = a.x; As[c4 + 1][row] = a.y;
            As[c4 + 2][row] = a.z; As[c4 + 3][row] = a.w;
        }
        {
            int kk = tid >> 4;
            int j4 = (tid & 15) * 4;
            float4 b = *(const float4*)(Whz + (size_t)(k0 + kk) * R_SZ + j0 + j4);
            *(float4*)&Bs[kk][j4] = b;
        }
        __syncthreads();
        #pragma unroll
        for (int kk = 0; kk < 16; kk++) {
            float ar[4], br[4];
            *(float4*)ar = *(const float4*)&As[kk][ty * 4];
            *(float4*)br = *(const float4*)&Bs[kk][tx * 4];
            #pragma unroll
            for (int i = 0; i < 4; i++)
                #pragma unroll
                for (int j = 0; j < 4; j++)
                    acc[i][j] = fmaf(ar[i], br[j], acc[i][j]);
        }
        __syncthreads();
    }
    #pragma unroll
    for (int i = 0; i < 4; i++) {
        float4 v = make_float4(acc[i][0], acc[i][1], acc[i][2], acc[i][3]);
        *(float4*)(g_Mz + (size_t)(i0 + ty * 4 + i) * R_SZ + j0 + tx * 4) = v;
    }
}

// ==================== Precompute xh/xz with HMMA + cp.async ====================
#define PP_ROW_B 80
#define PP_PLANE 10240
#define PP_SMEM (8 * PP_PLANE)

__global__ void __launch_bounds__(256) precompute_mma(const float* __restrict__ bh,
                                                      const float* __restrict__ bz) {
    extern __shared__ char psm[];
    const uint32_t sb = smem_u32(psm);
    const int tid = threadIdx.x, warp = tid >> 5, lane = tid & 31;
    const long m_blk = (long)blockIdx.y * 128;
    const int  n_blk = blockIdx.x * 128;

    const float* bias; float* dst; int rb;
    if (n_blk < R_SZ) { bias = bh; dst = g_xh; rb = n_blk; }
    else              { bias = bz; dst = g_xz; rb = n_blk - R_SZ; }

    const int m0w = (warp & 1) * 64;
    const int n0w = (warp >> 1) * 32;

    float acc[4][4][4];
    #pragma unroll
    for (int a = 0; a < 4; a++)
        #pragma unroll
        for (int b = 0; b < 4; b++)
            #pragma unroll
            for (int c = 0; c < 4; c++) acc[a][b][c] = 0.0f;

    auto stage = [&](int buf, int k0) {
        #pragma unroll
        for (int r = 0; r < 2; r++) {
            int cid = tid + r * 256;
            int row = cid >> 2;
            int qt  = cid & 3;
            uint32_t dA = sb + (uint32_t)((buf * 4 + 0) * PP_PLANE) + (uint32_t)row * PP_ROW_B + (uint32_t)qt * 16;
            uint32_t dB = sb + (uint32_t)((buf * 4 + 2) * PP_PLANE) + (uint32_t)row * PP_ROW_B + (uint32_t)qt * 16;
            size_t sa = (size_t)(m_blk + row) * D_SZ + k0 + qt * 8;
            size_t sw = (size_t)(n_blk + row) * D_SZ + k0 + qt * 8;
            cp_async16(dA,              g_x_hi + sa);
            cp_async16(dA + PP_PLANE,   g_x_lo + sa);
            cp_async16(dB,              g_w_hi + sw);
            cp_async16(dB + PP_PLANE,   g_w_lo + sw);
        }
    };

    int buf = 0;
    stage(0, 0);
    CP_COMMIT();
    for (int s = 0; s < D_SZ / 32; s++) {
        if (s + 1 < D_SZ / 32) { stage(buf ^ 1, (s + 1) * 32); CP_COMMIT(); CP_WAIT1(); }
        else                   { CP_WAIT0(); }
        __syncthreads();

        const uint32_t AhS = sb + (uint32_t)((buf * 4 + 0) * PP_PLANE);
        const uint32_t AlS = AhS + PP_PLANE;
        const char* Bh = psm + (buf * 4 + 2) * PP_PLANE;
        const char* Bl = Bh + PP_PLANE;
        #pragma unroll
        for (int k16 = 0; k16 < 2; k16++) {
            uint32_t ahi[4][4], alo[4][4];
            #pragma unroll
            for (int mi = 0; mi < 4; mi++) {
                uint32_t ar = (uint32_t)(m0w + mi * 16 + (lane & 15)) * PP_ROW_B
                            + (uint32_t)(lane >> 4) * 16 + (uint32_t)k16 * 32;
                ldsm_x4(ahi[mi], AhS + ar);
                ldsm_x4(alo[mi], AlS + ar);
            }
            uint32_t bhw[4][2], blw[4][2];
            #pragma unroll
            for (int ni = 0; ni < 4; ni++) {
                uint32_t bo = (uint32_t)(n0w + ni * 8 + (lane >> 2)) * PP_ROW_B
                            + (uint32_t)((lane & 3) * 2) * 2 + (uint32_t)k16 * 32;
                bhw[ni][0] = *(const uint32_t*)(Bh + bo);
                bhw[ni][1] = *(const uint32_t*)(Bh + bo + 16);
                blw[ni][0] = *(const uint32_t*)(Bl + bo);
                blw[ni][1] = *(const uint32_t*)(Bl + bo + 16);
            }
            #pragma unroll
            for (int mi = 0; mi < 4; mi++)
                #pragma unroll
                for (int ni = 0; ni < 4; ni++) {
                    mma_bf16(acc[mi][ni], ahi[mi], bhw[ni][0], bhw[ni][1]);
                    mma_bf16(acc[mi][ni], ahi[mi], blw[ni][0], blw[ni][1]);
                    mma_bf16(acc[mi][ni], alo[mi], bhw[ni][0], bhw[ni][1]);
                }
        }
        __syncthreads();
        buf ^= 1;
    }

    #pragma unroll
    for (int ni = 0; ni < 4; ni++) {
        int col = n0w + ni * 8 + (lane & 3) * 2;
        float2 bv = *(const float2*)(bias + rb + col);
        #pragma unroll
        for (int mi = 0; mi < 4; mi++) {
            #pragma unroll
            for (int half = 0; half < 2; half++) {
                long m = m_blk + m0w + mi * 16 + (lane >> 2) + half * 8;
                int b = (int)(m >> 9), t = (int)(m & 511);
                float2 v;
                v.x = acc[mi][ni][half * 2 + 0] + bv.x;
                v.y = acc[mi][ni][half * 2 + 1] + bv.y;
                *(float2*)(dst + ((long)t * B_SZ + b) * R_SZ + rb + col) = v;
            }
        }
    }
}

// ==================== Persistent warp-MMA scan (16 warps, 4 independent groups) ====================
// 64 CTAs x 512 threads. CTA owns r-slice [cta*16, +16).
// Group g (warps 4g..4g+3, threads [128g,128g+128)) owns m-stripe rows [16g,16g+16):
// stages ONLY its 16 h-rows (private double-buffered SMEM), syncs with named barrier 1+g.
// Within group: q = warp&3; q<2 -> h n-tile q*8, q>=2 -> z n-tile (q-2)*8.
#define NCTA 64
#define KC 128
#define NCHUNK (R_SZ / KC)                   // 8
#define B_ROW_BYTES 2064                     // (1024+8) bf16
#define A_ROW_BYTES 272                      // (128+8) bf16
#define GRP_PLANE (16 * A_ROW_BYTES)         // 4352
#define GRP_BUFS (4 * GRP_PLANE)             // 17408: [buf0 hi, buf0 lo, buf1 hi, buf1 lo]
#define OFF_BHI 0
#define OFF_BLO (32 * B_ROW_BYTES)           // 66048
#define OFF_A   (2 * 32 * B_ROW_BYTES)       // 132096
#define OFF_Z   (OFF_A + 4 * GRP_BUFS)       // 201728
#define Z_STRIDE 18
#define SCAN_SMEM (OFF_Z + 64 * Z_STRIDE * 4)  // 206336

__global__ void __launch_bounds__(512) scan_kernel(const float* __restrict__ Whh) {
    extern __shared__ char smem[];
    const uint32_t sbase = smem_u32(smem);
    float* zbuf = (float*)(smem + OFF_Z);
    const int tid  = threadIdx.x;
    const int warp = tid >> 5;
    const int lane = tid & 31;
    const int gid  = warp >> 2;              // group 0..3 (m-stripe)
    const int gtid = tid & 127;              // thread within group
    const int barid = 1 + gid;
    const int r_base = blockIdx.x * 16;

    // one-time: weights -> SMEM bf16 hi/lo (whole block)
    for (int i = tid; i < 32 * R_SZ; i += 512) {
        int j = i >> 10;
        int k = i & 1023;
        float w = (j < 16) ? Whh[(size_t)(r_base + j) * R_SZ + k]
                           : g_Mz[(size_t)(r_base + j - 16) * R_SZ + k];
        __nv_bfloat16 h = __float2bfloat16_rn(w);
        __nv_bfloat16 l = __float2bfloat16_rn(w - __bfloat162float(h));
        *(unsigned short*)(smem + OFF_BHI + j * B_ROW_BYTES + k * 2) = __bfloat16_as_ushort(h);
        *(unsigned short*)(smem + OFF_BLO + j * B_ROW_BYTES + k * 2) = __bfloat16_as_ushort(l);
    }
    __syncthreads();

    const int m0 = gid * 16;                 // group's m-stripe
    const int q  = warp & 3;                 // n-tile (0,1=h; 2,3=z)
    const bool is_h = (q < 2);

    const int rrow = lane >> 2;              // 0..7
    const int jc   = (lane & 3) * 2;         // 0,2,4,6
    const int rc   = (q & 1) * 8 + jc;       // r-col within 16-slice
    const int jg   = r_base + rc;            // global r
    const int brow0 = m0 + rrow, brow1 = brow0 + 8;

    const uint32_t b_off = (uint32_t)(q * 8 + rrow) * B_ROW_BYTES + (uint32_t)jc * 2;
    // ldmatrix row within the group's private 16-row buffer (local rows 0..15)
    const uint32_t a_row_off = (uint32_t)(lane & 15) * A_ROW_BYTES + (uint32_t)(lane >> 4) * 16;
    const uint32_t grpA = (uint32_t)OFF_A + (uint32_t)gid * GRP_BUFS;

    float hold[2][2] = {};

    for (int t = 0; t < T_SZ; t++) {
        float xv[2][2];
        {
            const float* src = (is_h ? g_xh : g_xz) + (size_t)t * (B_SZ * R_SZ);
            float2 a0 = __ldg((const float2*)(src + (size_t)brow0 * R_SZ + jg));
            float2 a1 = __ldg((const float2*)(src + (size_t)brow1 * R_SZ + jg));
            xv[0][0] = a0.x; xv[0][1] = a0.y; xv[1][0] = a1.x; xv[1][1] = a1.y;
        }

        const unsigned short* hhi = g_h_hi[t & 1];
        const unsigned short* hlo = g_h_lo[t & 1];

        float d[4] = {0.0f, 0.0f, 0.0f, 0.0f};

        // group stage: its 16 rows x 128 cols x 2 planes = 512 x 16B, 4 per thread
        auto stage = [&](int buf, int kc) {
            #pragma unroll
            for (int r = 0; r < 4; r++) {
                int cid   = gtid + r * 128;          // 0..511
                int plane = cid >> 8;                // 0..1
                int rem   = cid & 255;
                int row   = rem >> 4;                // 0..15 (local)
                int c16   = rem & 15;
                uint32_t dA = sbase + grpA + (uint32_t)buf * (2 * GRP_PLANE)
                            + (uint32_t)plane * GRP_PLANE
                            + (uint32_t)row * A_ROW_BYTES + (uint32_t)c16 * 16;
                const unsigned short* sp = plane ? hlo : hhi;
                cp_async16(dA, sp + (size_t)(m0 + row) * R_SZ + kc + c16 * 8);
            }
        };

        stage(0, 0);
        CP_COMMIT();
        for (int c = 0; c < NCHUNK; c++) {
            if (c + 1 < NCHUNK) { stage((c + 1) & 1, (c + 1) * KC); CP_COMMIT(); CP_WAIT1(); }
            else                { CP_WAIT0(); }
            BAR_SYNC(barid, 128);            // group's staged data visible

            const int buf = c & 1;
            const uint32_t a_hi_base = sbase + grpA + (uint32_t)buf * (2 * GRP_PLANE);
            const uint32_t a_lo_base = a_hi_base + GRP_PLANE;
            const char* bsm = smem;

            #pragma unroll
            for (int kb = 0; kb < KC / 16; kb++) {
                const uint32_t kloc = (uint32_t)kb * 32;
                uint32_t ahi[4], alo[4];
                ldsm_x4(ahi, a_hi_base + a_row_off + kloc);
                ldsm_x4(alo, a_lo_base + a_row_off + kloc);

                uint32_t kB = (uint32_t)(c * KC) * 2 + kloc;
                uint32_t b0h = *(const uint32_t*)(bsm + OFF_BHI + b_off + kB);
                uint32_t b1h = *(const uint32_t*)(bsm + OFF_BHI + b_off + kB + 16);
                uint32_t b0l = *(const uint32_t*)(bsm + OFF_BLO + b_off + kB);
                uint32_t b1l = *(const uint32_t*)(bsm + OFF_BLO + b_off + kB + 16);

                mma_bf16(d, ahi, b0h, b1h);
                mma_bf16(d, ahi, b0l, b1l);
                mma_bf16(d, alo, b0h, b1h);
            }
            BAR_SYNC(barid, 128);            // all group reads of buf done before re-stage
        }

        // z-warps: sigmoid -> zbuf (rows are group-private)
        if (!is_h) {
            #pragma unroll
            for (int qq = 0; qq < 2; qq++) {
                int br = (qq == 0) ? brow0 : brow1;
                float2 zv;
                zv.x = 1.0f / (1.0f + expf(-(d[qq * 2 + 0] + xv[qq][0])));
                zv.y = 1.0f / (1.0f + expf(-(d[qq * 2 + 1] + xv[qq][1])));
                *(float2*)&zbuf[br * Z_STRIDE + rc] = zv;
            }
        }
        BAR_SYNC(barid, 128);
        // h-warps: gate + write h
        if (is_h) {
            unsigned short* dhi = g_h_hi[(t + 1) & 1];
            unsigned short* dlo = g_h_lo[(t + 1) & 1];
            #pragma unroll
            for (int qq = 0; qq < 2; qq++) {
                int br = (qq == 0) ? brow0 : brow1;
                float2 zv = *(const float2*)&zbuf[br * Z_STRIDE + rc];
                float hb0 = fmaxf(d[qq * 2 + 0] + xv[qq][0], 0.0f);
                float hb1 = fmaxf(d[qq * 2 + 1] + xv[qq][1], 0.0f);
                float hn0 = zv.x * hold[qq][0] + (1.0f - zv.x) * hb0;
                float hn1 = zv.y * hold[qq][1] + (1.0f - zv.y) * hb1;
                hold[qq][0] = hn0; hold[qq][1] = hn1;
                size_t o = (size_t)br * R_SZ + jg;
                *(uint32_t*)(dhi + o) = pack2_hi(hn0, hn1);
                *(uint32_t*)(dlo + o) = pack2_lo(hn0, hn1);
                if (t == T_SZ - 1) {
                    g_hf[o] = hn0; g_hf[o + 1] = hn1;
                }
            }
        }

        // grid barrier over 64 CTAs (block-wide)
        __threadfence();
        __syncthreads();
        if (tid == 0) {
            atomicAdd(&g_arrive, 1u);
            unsigned target = (unsigned)NCTA * (unsigned)(t + 1);
            while (*((volatile unsigned*)&g_arrive) < target) { }
            __threadfence();
        }
        __syncthreads();
    }
}

// ==================== Output: y = h_final @ Wy^T + by ====================
__global__ void __launch_bounds__(128) output_kernel(const float* __restrict__ Wy,
                                                     const float* __restrict__ by,
                                                     float* __restrict__ out) {
    __shared__ float shh[R_SZ];
    const int b = blockIdx.x;
    const int o = blockIdx.y * 128 + threadIdx.x;
    const float* hrow = g_hf + (size_t)b * R_SZ;
    #pragma unroll
    for (int v = 0; v < 2; v++) {
        int i4 = threadIdx.x + v * 128;
        ((float4*)shh)[i4] = *(const float4*)(hrow + i4 * 4);
    }
    __syncthreads();
    float acc = __ldg(&by[o]);
    const float* wrow = Wy + (size_t)o * R_SZ;
    #pragma unroll 8
    for (int k4 = 0; k4 < R_SZ / 4; k4++) {
        float4 h4 = ((const float4*)shh)[k4];
        float4 w4 = __ldg((const float4*)(wrow + k4 * 4));
        acc = fmaf(h4.x, w4.x, acc); acc = fmaf(h4.y, w4.y, acc);
        acc = fmaf(h4.z, w4.z, acc); acc = fmaf(h4.w, w4.w, acc);
    }
    out[(size_t)b * O_SZ + o] = acc;
}

// ==================== launch ====================
extern "C" void kernel_launch(void* const* d_in, const int* in_sizes, int n_in,
                              void* d_out, int out_size) {
    const float* x   = (const float*)d_in[0];
    const float* Wxh = (const float*)d_in[1];
    const float* bh  = (const float*)d_in[2];
    const float* Whh = (const float*)d_in[3];
    const float* Wxz = (const float*)d_in[4];
    const float* bz  = (const float*)d_in[5];
    const float* Whz = (const float*)d_in[6];
    const float* Wy  = (const float*)d_in[7];
    const float* by  = (const float*)d_in[8];
    float* out = (float*)d_out;

    static bool attr_set = false;
    if (!attr_set) {
        cudaFuncSetAttribute(scan_kernel,
                             cudaFuncAttributeMaxDynamicSharedMemorySize, SCAN_SMEM);
        cudaFuncSetAttribute(precompute_mma,
                             cudaFuncAttributeMaxDynamicSharedMemorySize, PP_SMEM);
        attr_set = true;
    }

    unsigned short *xhi_p, *xlo_p, *whi_p, *wlo_p;
    cudaGetSymbolAddress((void**)&xhi_p, g_x_hi);
    cudaGetSymbolAddress((void**)&xlo_p, g_x_lo);
    cudaGetSymbolAddress((void**)&whi_p, g_w_hi);
    cudaGetSymbolAddress((void**)&wlo_p, g_w_lo);
    split_kernel<<<(int)((size_t)M_SZ * D_SZ / 1024), 256>>>(x, xhi_p, xlo_p);
    split_kernel<<<(R_SZ * D_SZ) / 1024, 256>>>(Wxh, whi_p, wlo_p);
    split_kernel<<<(R_SZ * D_SZ) / 1024, 256>>>(Wxz, whi_p + (size_t)R_SZ * D_SZ,
                                                wlo_p + (size_t)R_SZ * D_SZ);

    mz_kernel<<<dim3(R_SZ / 64, R_SZ / 64), 256>>>(Wxz, Whz);
    precompute_mma<<<dim3(2048 / 128, M_SZ / 128), 256, PP_SMEM>>>(bh, bz);
    init_kernel<<<(B_SZ * R_SZ + 255) / 256, 256>>>();
    scan_kernel<<<NCTA, 512, SCAN_SMEM>>>(Whh);
    output_kernel<<<dim3(B_SZ, O_SZ / 128), 128>>>(Wy, by, out);
}